// round 1
// baseline (speedup 1.0000x reference)
#include <cuda_runtime.h>
#include <cstdint>

#define N_NODES 100000
#define N_EDGES 1600000
#define D 64

// ---------------- static scratch (no runtime allocation allowed) ----------------
__device__ __align__(16) float g_deg[N_NODES];
__device__ __align__(16) float g_inv[N_NODES];
__device__ __align__(16) float g_xl [N_NODES * D];  // x@Wl^T  (layer1), then h@W2l^T (layer2)
__device__ __align__(16) float g_p1 [N_NODES * D];  // x@W1r^T + b1
__device__ __align__(16) float g_p2 [N_NODES * D];  // h@W2r^T + b2
__device__ __align__(16) float g_agg[N_NODES * D];  // scatter accumulator (reused)

// ---------------- kernels ----------------

// Zero the accumulator (and optionally deg).
__global__ void k_clear(int clear_deg) {
    int i = blockIdx.x * blockDim.x + threadIdx.x;
    int stride = gridDim.x * blockDim.x;
    float4 z = make_float4(0.f, 0.f, 0.f, 0.f);
    float4* a = reinterpret_cast<float4*>(g_agg);
    const int n4 = N_NODES * D / 4;
    for (int j = i; j < n4; j += stride) a[j] = z;
    if (clear_deg) {
        for (int j = i; j < N_NODES; j += stride) g_deg[j] = 0.f;
    }
}

// In-degree via float atomics.
__global__ void k_deg(const int* __restrict__ dst) {
    int e = blockIdx.x * blockDim.x + threadIdx.x;
    if (e < N_EDGES) atomicAdd(&g_deg[dst[e]], 1.0f);
}

__global__ void k_inv() {
    int i = blockIdx.x * blockDim.x + threadIdx.x;
    if (i < N_NODES) g_inv[i] = 1.0f / fmaxf(g_deg[i], 1.0f);
}

// Dual GEMM: per 16-node tile compute  xl = in @ Wl^T  and  p = in @ Wr^T + b.
// LAYER==2: input row is computed on the fly as relu(agg*inv + p1) (fused layer-1 epilogue).
// 1024 threads: thread t owns (node = t>>6, out = t&63).
template <int LAYER>
__global__ __launch_bounds__(1024) void k_gemm(const float* __restrict__ x,
                                               const float* __restrict__ Wl,
                                               const float* __restrict__ Wr,
                                               const float* __restrict__ b) {
    __shared__ float sx[16][D];
    __shared__ float swl[D][D];  // transposed: swl[k][out]
    __shared__ float swr[D][D];

    const int tid  = threadIdx.x;
    const int node = tid >> 6;
    const int out  = tid & 63;
    const int gn   = blockIdx.x * 16 + node;

    // Load weights transposed (4096 elems each, 4 per thread).
    #pragma unroll
    for (int i = tid; i < D * D; i += 1024) {
        int r = i >> 6, c = i & 63;
        swl[c][r] = Wl[i];
        swr[c][r] = Wr[i];
    }
    // Load / compute input tile row.
    float v = 0.f;
    if (gn < N_NODES) {
        if (LAYER == 1) {
            v = x[gn * D + out];
        } else {
            v = fmaxf(g_agg[gn * D + out] * g_inv[gn] + g_p1[gn * D + out], 0.f);
        }
    }
    sx[node][out] = v;
    __syncthreads();

    float accl = 0.f;
    float accr = b[out];
    #pragma unroll
    for (int k = 0; k < D; k++) {
        float xv = sx[node][k];          // broadcast within the 64-thread node group
        accl = fmaf(xv, swl[k][out], accl);
        accr = fmaf(xv, swr[k][out], accr);
    }
    if (gn < N_NODES) {
        g_xl[gn * D + out] = accl;
        if (LAYER == 1) g_p1[gn * D + out] = accr;
        else            g_p2[gn * D + out] = accr;
    }
}

// Edge scatter: agg[dst] += xl[src], 16B-vector atomic reductions.
// One thread per (edge, 16B chunk): 16 consecutive threads cover one edge's 256B row.
__global__ void k_scatter(const int* __restrict__ src, const int* __restrict__ dst) {
    int idx = blockIdx.x * blockDim.x + threadIdx.x;
    if (idx >= N_EDGES * 16) return;
    const int e = idx >> 4;
    const int c = (idx & 15) << 2;
    const int s = src[e];
    const int d = dst[e];
    const float4 v = *reinterpret_cast<const float4*>(&g_xl[s * D + c]);
    float4* p = reinterpret_cast<float4*>(&g_agg[d * D + c]);
    asm volatile("red.global.add.v4.f32 [%0], {%1, %2, %3, %4};"
                 :: "l"(p), "f"(v.x), "f"(v.y), "f"(v.z), "f"(v.w)
                 : "memory");
}

// Final epilogue: out = agg*inv + p2 (no relu on layer 2).
__global__ void k_out(float* __restrict__ out) {
    int i = blockIdx.x * blockDim.x + threadIdx.x;
    const int n4 = N_NODES * D / 4;
    if (i < n4) {
        const int node = i >> 4;
        const float inv = g_inv[node];
        float4 a = reinterpret_cast<const float4*>(g_agg)[i];
        float4 p = reinterpret_cast<const float4*>(g_p2)[i];
        float4 r;
        r.x = fmaf(a.x, inv, p.x);
        r.y = fmaf(a.y, inv, p.y);
        r.z = fmaf(a.z, inv, p.z);
        r.w = fmaf(a.w, inv, p.w);
        reinterpret_cast<float4*>(out)[i] = r;
    }
}

// ---------------- launch ----------------
extern "C" void kernel_launch(void* const* d_in, const int* in_sizes, int n_in,
                              void* d_out, int out_size) {
    const float* x   = (const float*)d_in[0];
    const int*   ei  = (const int*)  d_in[1];
    const float* W1l = (const float*)d_in[2];
    const float* b1  = (const float*)d_in[3];
    const float* W1r = (const float*)d_in[4];
    const float* W2l = (const float*)d_in[5];
    const float* b2  = (const float*)d_in[6];
    const float* W2r = (const float*)d_in[7];
    const int* src = ei;
    const int* dst = ei + N_EDGES;

    const int GEMM_BLOCKS   = (N_NODES + 15) / 16;            // 6250
    const int SCATTER_ITEMS = N_EDGES * 16;                   // 25.6M
    const int SCATTER_GRID  = (SCATTER_ITEMS + 255) / 256;
    const int EW_GRID       = (N_NODES * D / 4 + 255) / 256;  // 1.6M items

    k_clear<<<2048, 256>>>(1);                                    // zero deg + agg
    k_deg<<<(N_EDGES + 255) / 256, 256>>>(dst);
    k_inv<<<(N_NODES + 255) / 256, 256>>>();
    k_gemm<1><<<GEMM_BLOCKS, 1024>>>(x, W1l, W1r, b1);            // xl, p1
    k_scatter<<<SCATTER_GRID, 256>>>(src, dst);                   // agg += xl[src]
    k_gemm<2><<<GEMM_BLOCKS, 1024>>>(nullptr, W2l, W2r, b2);      // h=relu(...); hl, p2
    k_clear<<<2048, 256>>>(0);                                    // zero agg
    k_scatter<<<SCATTER_GRID, 256>>>(src, dst);                   // agg += hl[src]
    k_out<<<EW_GRID, 256>>>((float*)d_out);
}

// round 2
// speedup vs baseline: 2.3019x; 2.3019x over previous
#include <cuda_runtime.h>
#include <cstdint>

#define N_NODES 100000
#define N_EDGES 1600000
#define D 64

// ---------------- static scratch (no runtime allocation allowed) ----------------
__device__ __align__(16) float g_deg[N_NODES];
__device__ __align__(16) float g_inv[N_NODES];
__device__ __align__(16) float g_xl [N_NODES * D];  // x@Wl^T  (layer1), then h@W2l^T (layer2)
__device__ __align__(16) float g_p1 [N_NODES * D];  // x@W1r^T + b1
__device__ __align__(16) float g_p2 [N_NODES * D];  // h@W2r^T + b2
__device__ __align__(16) float g_agg[N_NODES * D];  // scatter accumulator (reused)

// ---------------- kernels ----------------

__global__ void k_clear(int clear_deg) {
    int i = blockIdx.x * blockDim.x + threadIdx.x;
    int stride = gridDim.x * blockDim.x;
    float4 z = make_float4(0.f, 0.f, 0.f, 0.f);
    float4* a = reinterpret_cast<float4*>(g_agg);
    const int n4 = N_NODES * D / 4;
    for (int j = i; j < n4; j += stride) a[j] = z;
    if (clear_deg) {
        for (int j = i; j < N_NODES; j += stride) g_deg[j] = 0.f;
    }
}

__global__ void k_deg(const int* __restrict__ dst) {
    int e = blockIdx.x * blockDim.x + threadIdx.x;
    if (e < N_EDGES) atomicAdd(&g_deg[dst[e]], 1.0f);
}

__global__ void k_inv() {
    int i = blockIdx.x * blockDim.x + threadIdx.x;
    if (i < N_NODES) g_inv[i] = 1.0f / fmaxf(g_deg[i], 1.0f);
}

// XOR-swizzled address into a [64][64] transposed weight tile: logical (k, out).
// Store (from global row-major [out][k]) is conflict-free; read is 2-way max.
__device__ __forceinline__ int wsw(int k, int out) {
    return k * 64 + (out ^ (k & 31));
}

// Dual register-blocked GEMM:  xl = in @ Wl^T,  p = in @ Wr^T + b.
// LAYER==2: input row computed on the fly as relu(agg*inv + p1).
// Block: 256 threads handle 256 nodes (4 chunks of 64) x 64 outs.
// Thread (tx = tid&15, ty = tid>>4) owns 4 nodes x 4 outs per chunk, both matrices.
template <int LAYER>
__global__ __launch_bounds__(256) void k_gemm(const float* __restrict__ x,
                                              const float* __restrict__ Wl,
                                              const float* __restrict__ Wr,
                                              const float* __restrict__ b) {
    __shared__ float swl[D * D];      // transposed + swizzled: wsw(k, out)
    __shared__ float swr[D * D];
    __shared__ float sx[64 * D];      // row-major [node][k]

    const int tid = threadIdx.x;
    const int tx  = tid & 15;         // out group: outs 4*tx .. 4*tx+3
    const int ty  = tid >> 4;         // node group: nodes 4*ty .. 4*ty+3

    // Load weights transposed+swizzled (conflict-free stores).
    #pragma unroll
    for (int i = tid; i < D * D; i += 256) {
        const int out = i >> 6, k = i & 63;
        swl[wsw(k, out)] = Wl[i];
        swr[wsw(k, out)] = Wr[i];
    }

    const float4 bias = reinterpret_cast<const float4*>(b)[tx];
    const int base = blockIdx.x * 256;

    for (int chunk = 0; chunk < 4; chunk++) {
        const int cbase = base + chunk * 64;
        __syncthreads();  // protect sx from previous iteration's readers

        // Load 64-node input chunk into sx (coalesced float4, conflict-free).
        {
            const int node = tid >> 4;   // 0..15
            const int kq   = tid & 15;   // float4 index 0..15
            #pragma unroll
            for (int nn = 0; nn < 4; nn++) {
                const int n  = nn * 16 + node;
                const int gn = cbase + n;
                float4 v = make_float4(0.f, 0.f, 0.f, 0.f);
                if (gn < N_NODES) {
                    if (LAYER == 1) {
                        v = *reinterpret_cast<const float4*>(&x[gn * D + kq * 4]);
                    } else {
                        const float inv = g_inv[gn];
                        const float4 a = *reinterpret_cast<const float4*>(&g_agg[gn * D + kq * 4]);
                        const float4 p = *reinterpret_cast<const float4*>(&g_p1 [gn * D + kq * 4]);
                        v.x = fmaxf(fmaf(a.x, inv, p.x), 0.f);
                        v.y = fmaxf(fmaf(a.y, inv, p.y), 0.f);
                        v.z = fmaxf(fmaf(a.z, inv, p.z), 0.f);
                        v.w = fmaxf(fmaf(a.w, inv, p.w), 0.f);
                    }
                }
                *reinterpret_cast<float4*>(&sx[n * D + kq * 4]) = v;
            }
        }
        __syncthreads();

        float accl[4][4], accr[4][4];
        #pragma unroll
        for (int r = 0; r < 4; r++) {
            accl[r][0] = 0.f;     accl[r][1] = 0.f;     accl[r][2] = 0.f;     accl[r][3] = 0.f;
            accr[r][0] = bias.x;  accr[r][1] = bias.y;  accr[r][2] = bias.z;  accr[r][3] = bias.w;
        }

        #pragma unroll 8
        for (int k = 0; k < D; k++) {
            float wl[4], wr[4], a[4];
            #pragma unroll
            for (int c = 0; c < 4; c++) {
                wl[c] = swl[wsw(k, 4 * tx + c)];
                wr[c] = swr[wsw(k, 4 * tx + c)];
            }
            #pragma unroll
            for (int r = 0; r < 4; r++) a[r] = sx[(ty * 4 + r) * D + k];
            #pragma unroll
            for (int r = 0; r < 4; r++)
                #pragma unroll
                for (int c = 0; c < 4; c++) {
                    accl[r][c] = fmaf(a[r], wl[c], accl[r][c]);
                    accr[r][c] = fmaf(a[r], wr[c], accr[r][c]);
                }
        }

        #pragma unroll
        for (int r = 0; r < 4; r++) {
            const int gn = cbase + ty * 4 + r;
            if (gn < N_NODES) {
                *reinterpret_cast<float4*>(&g_xl[gn * D + 4 * tx]) =
                    make_float4(accl[r][0], accl[r][1], accl[r][2], accl[r][3]);
                float* pdst = (LAYER == 1) ? g_p1 : g_p2;
                *reinterpret_cast<float4*>(&pdst[gn * D + 4 * tx]) =
                    make_float4(accr[r][0], accr[r][1], accr[r][2], accr[r][3]);
            }
        }
    }
}

// Edge scatter: agg[dst] += xl[src], 16B-vector atomic reductions.
__global__ void k_scatter(const int* __restrict__ src, const int* __restrict__ dst) {
    int idx = blockIdx.x * blockDim.x + threadIdx.x;
    if (idx >= N_EDGES * 16) return;
    const int e = idx >> 4;
    const int c = (idx & 15) << 2;
    const int s = src[e];
    const int d = dst[e];
    const float4 v = *reinterpret_cast<const float4*>(&g_xl[s * D + c]);
    float4* p = reinterpret_cast<float4*>(&g_agg[d * D + c]);
    asm volatile("red.global.add.v4.f32 [%0], {%1, %2, %3, %4};"
                 :: "l"(p), "f"(v.x), "f"(v.y), "f"(v.z), "f"(v.w)
                 : "memory");
}

// Final epilogue: out = agg*inv + p2 (no relu on layer 2).
__global__ void k_out(float* __restrict__ out) {
    int i = blockIdx.x * blockDim.x + threadIdx.x;
    const int n4 = N_NODES * D / 4;
    if (i < n4) {
        const int node = i >> 4;
        const float inv = g_inv[node];
        float4 a = reinterpret_cast<const float4*>(g_agg)[i];
        float4 p = reinterpret_cast<const float4*>(g_p2)[i];
        float4 r;
        r.x = fmaf(a.x, inv, p.x);
        r.y = fmaf(a.y, inv, p.y);
        r.z = fmaf(a.z, inv, p.z);
        r.w = fmaf(a.w, inv, p.w);
        reinterpret_cast<float4*>(out)[i] = r;
    }
}

// ---------------- launch ----------------
extern "C" void kernel_launch(void* const* d_in, const int* in_sizes, int n_in,
                              void* d_out, int out_size) {
    const float* x   = (const float*)d_in[0];
    const int*   ei  = (const int*)  d_in[1];
    const float* W1l = (const float*)d_in[2];
    const float* b1  = (const float*)d_in[3];
    const float* W1r = (const float*)d_in[4];
    const float* W2l = (const float*)d_in[5];
    const float* b2  = (const float*)d_in[6];
    const float* W2r = (const float*)d_in[7];
    const int* src = ei;
    const int* dst = ei + N_EDGES;

    const int GEMM_BLOCKS   = (N_NODES + 255) / 256;          // 391
    const int SCATTER_ITEMS = N_EDGES * 16;                   // 25.6M
    const int SCATTER_GRID  = (SCATTER_ITEMS + 255) / 256;
    const int EW_GRID       = (N_NODES * D / 4 + 255) / 256;

    k_clear<<<2048, 256>>>(1);                                    // zero deg + agg
    k_deg<<<(N_EDGES + 255) / 256, 256>>>(dst);
    k_inv<<<(N_NODES + 255) / 256, 256>>>();
    k_gemm<1><<<GEMM_BLOCKS, 256>>>(x, W1l, W1r, b1);             // xl, p1
    k_scatter<<<SCATTER_GRID, 256>>>(src, dst);                   // agg += xl[src]
    k_gemm<2><<<GEMM_BLOCKS, 256>>>(nullptr, W2l, W2r, b2);       // h=relu(...); hl, p2
    k_clear<<<2048, 256>>>(0);                                    // zero agg
    k_scatter<<<SCATTER_GRID, 256>>>(src, dst);                   // agg += hl[src]
    k_out<<<EW_GRID, 256>>>((float*)d_out);
}

// round 5
// speedup vs baseline: 3.2441x; 1.4093x over previous
#include <cuda_runtime.h>
#include <cstdint>

#define N_NODES 100000
#define N_EDGES 1600000
#define D 64
#define SCAN_NB 98            // ceil(100000/1024)

// ---------------- static scratch (device-code access ONLY — never passed from host) ----
__device__ int   g_deg_i[N_NODES];
__device__ int   g_rp[N_NODES + 1];       // CSR row pointers (by dst)
__device__ int   g_bsum[128];
__device__ int   g_cnt[N_NODES];
__device__ int   g_col[N_EDGES];          // CSR column (src) indices
__device__ float g_inv[N_NODES];
__device__ __align__(16) float g_xl[N_NODES * D];  // in @ Wl^T (per layer)
__device__ __align__(16) float g_p [N_NODES * D];  // in @ Wr^T + b (per layer)
__device__ __align__(16) float g_h [N_NODES * D];  // layer-1 output

// ---------------- CSR build ----------------

__global__ void k_zero_deg() {
    int i = blockIdx.x * blockDim.x + threadIdx.x;
    if (i < N_NODES) g_deg_i[i] = 0;
}

__global__ void k_deg(const int* __restrict__ dst) {
    int e = blockIdx.x * blockDim.x + threadIdx.x;
    if (e < N_EDGES) atomicAdd(&g_deg_i[dst[e]], 1);
}

// Block-level inclusive scan (1024 wide); writes rp[i+1] (partial) + block totals.
__global__ __launch_bounds__(1024) void k_scan1() {
    __shared__ int s[1024];
    const int t = threadIdx.x, b = blockIdx.x;
    const int i = b * 1024 + t;
    s[t] = (i < N_NODES) ? g_deg_i[i] : 0;
    __syncthreads();
    for (int off = 1; off < 1024; off <<= 1) {
        int u = (t >= off) ? s[t - off] : 0;
        __syncthreads();
        s[t] += u;
        __syncthreads();
    }
    if (i < N_NODES) g_rp[i + 1] = s[t];
    if (t == 1023) g_bsum[b] = s[t];
}

// Scan the block totals (single block, 128 threads >= 98 blocks).
__global__ void k_scan2() {
    __shared__ int s[128];
    const int t = threadIdx.x;
    s[t] = (t < SCAN_NB) ? g_bsum[t] : 0;
    __syncthreads();
    for (int off = 1; off < 128; off <<= 1) {
        int u = (t >= off) ? s[t - off] : 0;
        __syncthreads();
        s[t] += u;
        __syncthreads();
    }
    g_bsum[t] = s[t];
}

// Add block offsets, zero fill counters, compute inv_deg, set rp[0].
__global__ void k_scan3() {
    int i = blockIdx.x * blockDim.x + threadIdx.x;
    if (i < N_NODES) {
        int b = i >> 10;
        if (b > 0) g_rp[i + 1] += g_bsum[b - 1];
        g_cnt[i] = 0;
        g_inv[i] = 1.0f / (float)max(g_deg_i[i], 1);
    }
    if (i == 0) g_rp[0] = 0;
}

__global__ void k_fill(const int* __restrict__ src, const int* __restrict__ dst) {
    int e = blockIdx.x * blockDim.x + threadIdx.x;
    if (e < N_EDGES) {
        const int d = dst[e];
        const int pos = atomicAdd(&g_cnt[d], 1);
        g_col[g_rp[d] + pos] = src[e];
    }
}

// ---------------- dual GEMM (round-2 proven inner loop) ----------------
// xl = in @ Wl^T,  p = in @ Wr^T + b.  LAYER==1: in = x arg; LAYER==2: in = g_h.
// Outputs always g_xl / g_p (globals, referenced in device code only).
__device__ __forceinline__ int wsw(int k, int out) {
    return k * 64 + (out ^ (k & 31));
}

template <int LAYER>
__global__ __launch_bounds__(256) void k_gemm(const float* __restrict__ xin,
                                              const float* __restrict__ Wl,
                                              const float* __restrict__ Wr,
                                              const float* __restrict__ b) {
    __shared__ float swl[D * D];      // transposed + swizzled: wsw(k, out)
    __shared__ float swr[D * D];
    __shared__ float sx[64 * D];      // row-major [node][k]

    const float* in = (LAYER == 1) ? xin : g_h;

    const int tid = threadIdx.x;
    const int tx  = tid & 15;
    const int ty  = tid >> 4;

    #pragma unroll
    for (int i = tid; i < D * D; i += 256) {
        const int out = i >> 6, k = i & 63;
        swl[wsw(k, out)] = Wl[i];
        swr[wsw(k, out)] = Wr[i];
    }

    const float4 bias = reinterpret_cast<const float4*>(b)[tx];
    const int base = blockIdx.x * 256;

    for (int chunk = 0; chunk < 4; chunk++) {
        const int cbase = base + chunk * 64;
        __syncthreads();

        {
            const int node = tid >> 4;
            const int kq   = tid & 15;
            #pragma unroll
            for (int nn = 0; nn < 4; nn++) {
                const int n  = nn * 16 + node;
                const int gn = cbase + n;
                float4 v = make_float4(0.f, 0.f, 0.f, 0.f);
                if (gn < N_NODES)
                    v = *reinterpret_cast<const float4*>(&in[gn * D + kq * 4]);
                *reinterpret_cast<float4*>(&sx[n * D + kq * 4]) = v;
            }
        }
        __syncthreads();

        float accl[4][4], accr[4][4];
        #pragma unroll
        for (int r = 0; r < 4; r++) {
            accl[r][0] = 0.f;     accl[r][1] = 0.f;     accl[r][2] = 0.f;     accl[r][3] = 0.f;
            accr[r][0] = bias.x;  accr[r][1] = bias.y;  accr[r][2] = bias.z;  accr[r][3] = bias.w;
        }

        #pragma unroll 8
        for (int k = 0; k < D; k++) {
            float wl[4], wr[4], a[4];
            #pragma unroll
            for (int c = 0; c < 4; c++) {
                wl[c] = swl[wsw(k, 4 * tx + c)];
                wr[c] = swr[wsw(k, 4 * tx + c)];
            }
            #pragma unroll
            for (int r = 0; r < 4; r++) a[r] = sx[(ty * 4 + r) * D + k];
            #pragma unroll
            for (int r = 0; r < 4; r++)
                #pragma unroll
                for (int c = 0; c < 4; c++) {
                    accl[r][c] = fmaf(a[r], wl[c], accl[r][c]);
                    accr[r][c] = fmaf(a[r], wr[c], accr[r][c]);
                }
        }

        #pragma unroll
        for (int r = 0; r < 4; r++) {
            const int gn = cbase + ty * 4 + r;
            if (gn < N_NODES) {
                *reinterpret_cast<float4*>(&g_xl[gn * D + 4 * tx]) =
                    make_float4(accl[r][0], accl[r][1], accl[r][2], accl[r][3]);
                *reinterpret_cast<float4*>(&g_p[gn * D + 4 * tx]) =
                    make_float4(accr[r][0], accr[r][1], accr[r][2], accr[r][3]);
            }
        }
    }
}

// ---------------- CSR gather-aggregate + fused epilogue ----------------
// One warp per node: lanes 0-15 / 16-31 each own a float4 column chunk and
// process alternate neighbors; pairwise shfl combine; epilogue fused.
// FINAL==0: relu, write g_h.  FINAL==1: no relu, write out arg (d_out).
template <int FINAL>
__global__ __launch_bounds__(256) void k_aggr(float4* __restrict__ out_arg) {
    const int warp = threadIdx.x >> 5, lane = threadIdx.x & 31;
    const int node = blockIdx.x * 8 + warp;
    if (node >= N_NODES) return;
    const int s0 = g_rp[node], s1 = g_rp[node + 1];
    const int c = lane & 15, h = lane >> 4;

    const float4* xl = reinterpret_cast<const float4*>(g_xl);
    const float4* p  = reinterpret_cast<const float4*>(g_p);

    float4 acc = make_float4(0.f, 0.f, 0.f, 0.f);
    for (int j = s0 + h; j < s1; j += 2) {
        const int s = g_col[j];
        const float4 v = xl[s * 16 + c];
        acc.x += v.x; acc.y += v.y; acc.z += v.z; acc.w += v.w;
    }
    acc.x += __shfl_xor_sync(0xffffffffu, acc.x, 16);
    acc.y += __shfl_xor_sync(0xffffffffu, acc.y, 16);
    acc.z += __shfl_xor_sync(0xffffffffu, acc.z, 16);
    acc.w += __shfl_xor_sync(0xffffffffu, acc.w, 16);

    if (h == 0) {
        const float inv = g_inv[node];
        const float4 pp = p[node * 16 + c];
        float4 r;
        r.x = fmaf(acc.x, inv, pp.x);
        r.y = fmaf(acc.y, inv, pp.y);
        r.z = fmaf(acc.z, inv, pp.z);
        r.w = fmaf(acc.w, inv, pp.w);
        if (FINAL == 0) {
            r.x = fmaxf(r.x, 0.f); r.y = fmaxf(r.y, 0.f);
            r.z = fmaxf(r.z, 0.f); r.w = fmaxf(r.w, 0.f);
            reinterpret_cast<float4*>(g_h)[node * 16 + c] = r;
        } else {
            out_arg[node * 16 + c] = r;
        }
    }
}

// ---------------- launch ----------------
extern "C" void kernel_launch(void* const* d_in, const int* in_sizes, int n_in,
                              void* d_out, int out_size) {
    const float* x   = (const float*)d_in[0];
    const int*   ei  = (const int*)  d_in[1];
    const float* W1l = (const float*)d_in[2];
    const float* b1  = (const float*)d_in[3];
    const float* W1r = (const float*)d_in[4];
    const float* W2l = (const float*)d_in[5];
    const float* b2  = (const float*)d_in[6];
    const float* W2r = (const float*)d_in[7];
    const int* src = ei;
    const int* dst = ei + N_EDGES;

    const int NGRID = (N_NODES + 255) / 256;
    const int EGRID = (N_EDGES + 255) / 256;
    const int GEMM_GRID = (N_NODES + 255) / 256;       // 391
    const int AGGR_GRID = (N_NODES + 7) / 8;           // 12500

    // CSR build (by dst)
    k_zero_deg<<<NGRID, 256>>>();
    k_deg<<<EGRID, 256>>>(dst);
    k_scan1<<<SCAN_NB, 1024>>>();
    k_scan2<<<1, 128>>>();
    k_scan3<<<NGRID, 256>>>();
    k_fill<<<EGRID, 256>>>(src, dst);

    // Layer 1
    k_gemm<1><<<GEMM_GRID, 256>>>(x, W1l, W1r, b1);
    k_aggr<0><<<AGGR_GRID, 256>>>(nullptr);

    // Layer 2
    k_gemm<2><<<GEMM_GRID, 256>>>(nullptr, W2l, W2r, b2);
    k_aggr<1><<<AGGR_GRID, 256>>>((float4*)d_out);
}

// round 6
// speedup vs baseline: 3.7081x; 1.1430x over previous
#include <cuda_runtime.h>
#include <cstdint>

#define N_NODES 100000
#define N_EDGES 1600000
#define D 64
#define SCAN_NB 98            // ceil(100000/1024)

// ---------------- static scratch (device-code access ONLY — never passed from host) ----
__device__ int   g_deg_i[N_NODES];
__device__ int   g_rp[N_NODES + 1];       // CSR row pointers (by dst)
__device__ int   g_bsum[128];
__device__ int   g_cnt[N_NODES];
__device__ int   g_col[N_EDGES];          // CSR column (src) indices
__device__ float g_inv[N_NODES];
__device__ __align__(16) float g_xl[N_NODES * D];  // in @ Wl^T (per layer)
__device__ __align__(16) float g_p [N_NODES * D];  // in @ Wr^T + b (per layer)
__device__ __align__(16) float g_h [N_NODES * D];  // layer-1 output

// ---------------- CSR build ----------------

__global__ void k_zero_deg() {
    int i = blockIdx.x * blockDim.x + threadIdx.x;
    if (i < N_NODES) g_deg_i[i] = 0;
}

__global__ void k_deg(const int* __restrict__ dst) {
    int e = blockIdx.x * blockDim.x + threadIdx.x;
    if (e < N_EDGES) atomicAdd(&g_deg_i[dst[e]], 1);
}

// Block-level inclusive scan (1024 wide); writes rp[i+1] (partial) + block totals.
__global__ __launch_bounds__(1024) void k_scan1() {
    __shared__ int s[1024];
    const int t = threadIdx.x, b = blockIdx.x;
    const int i = b * 1024 + t;
    s[t] = (i < N_NODES) ? g_deg_i[i] : 0;
    __syncthreads();
    for (int off = 1; off < 1024; off <<= 1) {
        int u = (t >= off) ? s[t - off] : 0;
        __syncthreads();
        s[t] += u;
        __syncthreads();
    }
    if (i < N_NODES) g_rp[i + 1] = s[t];
    if (t == 1023) g_bsum[b] = s[t];
}

// Scan the block totals (single block, 128 threads >= 98 blocks).
__global__ void k_scan2() {
    __shared__ int s[128];
    const int t = threadIdx.x;
    s[t] = (t < SCAN_NB) ? g_bsum[t] : 0;
    __syncthreads();
    for (int off = 1; off < 128; off <<= 1) {
        int u = (t >= off) ? s[t - off] : 0;
        __syncthreads();
        s[t] += u;
        __syncthreads();
    }
    g_bsum[t] = s[t];
}

// Add block offsets, zero fill counters, compute inv_deg, set rp[0].
__global__ void k_scan3() {
    int i = blockIdx.x * blockDim.x + threadIdx.x;
    if (i < N_NODES) {
        int b = i >> 10;
        if (b > 0) g_rp[i + 1] += g_bsum[b - 1];
        g_cnt[i] = 0;
        g_inv[i] = 1.0f / (float)max(g_deg_i[i], 1);
    }
    if (i == 0) g_rp[0] = 0;
}

__global__ void k_fill(const int* __restrict__ src, const int* __restrict__ dst) {
    int e = blockIdx.x * blockDim.x + threadIdx.x;
    if (e < N_EDGES) {
        const int d = dst[e];
        const int pos = atomicAdd(&g_cnt[d], 1);
        g_col[g_rp[d] + pos] = src[e];
    }
}

// ---------------- dual GEMM, float4-vectorized smem ----------------
// xl = in @ Wl^T,  p = in @ Wr^T + b.  LAYER==1: in = x arg; LAYER==2: in = g_h.
// 256 threads, 256 nodes (4 chunks of 64) x 64 outs.
// Thread (tx=tid&15, ty=tid>>4) owns a 4-node x 4-out tile for BOTH matrices.
// Weight smem: float4 rows [out][k4], float4-level XOR swizzle
//   slot = k4 ^ ((out>>2)&15): store conflict-free, read <=2-way.
template <int LAYER>
__global__ __launch_bounds__(256) void k_gemm(const float* __restrict__ xin,
                                              const float4* __restrict__ Wl,
                                              const float4* __restrict__ Wr,
                                              const float4* __restrict__ b) {
    __shared__ float4 swl[64 * 16];
    __shared__ float4 swr[64 * 16];
    __shared__ float4 sx [64 * 16];

    const float4* in = (LAYER == 1) ? reinterpret_cast<const float4*>(xin)
                                    : reinterpret_cast<const float4*>(g_h);

    const int tid = threadIdx.x;
    const int tx  = tid & 15;     // outs 4*tx .. 4*tx+3
    const int ty  = tid >> 4;     // nodes 4*ty .. 4*ty+3 (within chunk)

    // Load weights (1024 float4 each), swizzled at float4 granularity.
    #pragma unroll
    for (int i = tid; i < 1024; i += 256) {
        const int out = i >> 4, k4 = i & 15;
        const int f = (out << 4) | (k4 ^ ((out >> 2) & 15));
        swl[f] = Wl[i];
        swr[f] = Wr[i];
    }
    const float4 bias = b[tx];
    const int base = blockIdx.x * 256;

    for (int chunk = 0; chunk < 4; chunk++) {
        const int cbase = base + chunk * 64;
        __syncthreads();   // protect sx from previous iteration's readers
        #pragma unroll
        for (int i = tid; i < 1024; i += 256) {
            const int gn = cbase + (i >> 4);
            float4 v = make_float4(0.f, 0.f, 0.f, 0.f);
            if (gn < N_NODES) v = in[gn * 16 + (i & 15)];
            sx[i] = v;     // plain layout: [node][k4]
        }
        __syncthreads();

        float accl[4][4], accr[4][4];
        #pragma unroll
        for (int r = 0; r < 4; r++) {
            accl[r][0] = 0.f;    accl[r][1] = 0.f;    accl[r][2] = 0.f;    accl[r][3] = 0.f;
            accr[r][0] = bias.x; accr[r][1] = bias.y; accr[r][2] = bias.z; accr[r][3] = bias.w;
        }

        #pragma unroll 2
        for (int k4 = 0; k4 < 16; k4++) {
            float4 a0 = sx[(ty * 4 + 0) * 16 + k4];
            float4 a1 = sx[(ty * 4 + 1) * 16 + k4];
            float4 a2 = sx[(ty * 4 + 2) * 16 + k4];
            float4 a3 = sx[(ty * 4 + 3) * 16 + k4];
            #pragma unroll
            for (int c = 0; c < 4; c++) {
                const int out = tx * 4 + c;
                const int f = (out << 4) | (k4 ^ ((out >> 2) & 15));
                const float4 wl = swl[f];
                const float4 wr = swr[f];
                const float4 av[4] = {a0, a1, a2, a3};
                #pragma unroll
                for (int r = 0; r < 4; r++) {
                    float sl = accl[r][c], sr = accr[r][c];
                    sl = fmaf(av[r].x, wl.x, sl); sr = fmaf(av[r].x, wr.x, sr);
                    sl = fmaf(av[r].y, wl.y, sl); sr = fmaf(av[r].y, wr.y, sr);
                    sl = fmaf(av[r].z, wl.z, sl); sr = fmaf(av[r].z, wr.z, sr);
                    sl = fmaf(av[r].w, wl.w, sl); sr = fmaf(av[r].w, wr.w, sr);
                    accl[r][c] = sl; accr[r][c] = sr;
                }
            }
        }

        #pragma unroll
        for (int r = 0; r < 4; r++) {
            const int gn = cbase + ty * 4 + r;
            if (gn < N_NODES) {
                reinterpret_cast<float4*>(g_xl)[gn * 16 + tx] =
                    make_float4(accl[r][0], accl[r][1], accl[r][2], accl[r][3]);
                reinterpret_cast<float4*>(g_p)[gn * 16 + tx] =
                    make_float4(accr[r][0], accr[r][1], accr[r][2], accr[r][3]);
            }
        }
    }
}

// ---------------- CSR gather-aggregate + fused epilogue ----------------
// One warp per node: lanes 0-15 / 16-31 each own a float4 column chunk and
// process alternate neighbors; pairwise shfl combine; epilogue fused.
// FINAL==0: relu, write g_h.  FINAL==1: no relu, write out arg (d_out).
template <int FINAL>
__global__ __launch_bounds__(256) void k_aggr(float4* __restrict__ out_arg) {
    const int warp = threadIdx.x >> 5, lane = threadIdx.x & 31;
    const int node = blockIdx.x * 8 + warp;
    if (node >= N_NODES) return;
    const int s0 = g_rp[node], s1 = g_rp[node + 1];
    const int c = lane & 15, h = lane >> 4;

    const float4* xl = reinterpret_cast<const float4*>(g_xl);
    const float4* p  = reinterpret_cast<const float4*>(g_p);

    float4 acc = make_float4(0.f, 0.f, 0.f, 0.f);
    #pragma unroll 2
    for (int j = s0 + h; j < s1; j += 2) {
        const int s = g_col[j];
        const float4 v = xl[s * 16 + c];
        acc.x += v.x; acc.y += v.y; acc.z += v.z; acc.w += v.w;
    }
    acc.x += __shfl_xor_sync(0xffffffffu, acc.x, 16);
    acc.y += __shfl_xor_sync(0xffffffffu, acc.y, 16);
    acc.z += __shfl_xor_sync(0xffffffffu, acc.z, 16);
    acc.w += __shfl_xor_sync(0xffffffffu, acc.w, 16);

    if (h == 0) {
        const float inv = g_inv[node];
        const float4 pp = p[node * 16 + c];
        float4 r;
        r.x = fmaf(acc.x, inv, pp.x);
        r.y = fmaf(acc.y, inv, pp.y);
        r.z = fmaf(acc.z, inv, pp.z);
        r.w = fmaf(acc.w, inv, pp.w);
        if (FINAL == 0) {
            r.x = fmaxf(r.x, 0.f); r.y = fmaxf(r.y, 0.f);
            r.z = fmaxf(r.z, 0.f); r.w = fmaxf(r.w, 0.f);
            reinterpret_cast<float4*>(g_h)[node * 16 + c] = r;
        } else {
            out_arg[node * 16 + c] = r;
        }
    }
}

// ---------------- launch ----------------
extern "C" void kernel_launch(void* const* d_in, const int* in_sizes, int n_in,
                              void* d_out, int out_size) {
    const float* x   = (const float*)d_in[0];
    const int*   ei  = (const int*)  d_in[1];
    const float* W1l = (const float*)d_in[2];
    const float* b1  = (const float*)d_in[3];
    const float* W1r = (const float*)d_in[4];
    const float* W2l = (const float*)d_in[5];
    const float* b2  = (const float*)d_in[6];
    const float* W2r = (const float*)d_in[7];
    const int* src = ei;
    const int* dst = ei + N_EDGES;

    const int NGRID = (N_NODES + 255) / 256;
    const int EGRID = (N_EDGES + 255) / 256;
    const int GEMM_GRID = (N_NODES + 255) / 256;       // 391
    const int AGGR_GRID = (N_NODES + 7) / 8;           // 12500

    // CSR build (by dst)
    k_zero_deg<<<NGRID, 256>>>();
    k_deg<<<EGRID, 256>>>(dst);
    k_scan1<<<SCAN_NB, 1024>>>();
    k_scan2<<<1, 128>>>();
    k_scan3<<<NGRID, 256>>>();
    k_fill<<<EGRID, 256>>>(src, dst);

    // Layer 1
    k_gemm<1><<<GEMM_GRID, 256>>>(x, (const float4*)W1l, (const float4*)W1r, (const float4*)b1);
    k_aggr<0><<<AGGR_GRID, 256>>>(nullptr);

    // Layer 2
    k_gemm<2><<<GEMM_GRID, 256>>>(nullptr, (const float4*)W2l, (const float4*)W2r, (const float4*)b2);
    k_aggr<1><<<AGGR_GRID, 256>>>((float4*)d_out);
}

// round 7
// speedup vs baseline: 3.8629x; 1.0418x over previous
#include <cuda_runtime.h>
#include <cuda_fp16.h>
#include <cstdint>

#define N_NODES 100000
#define N_EDGES 1600000
#define D 64
#define SCAN_NB 98            // ceil(100000/1024)

// ---------------- static scratch (device-code access ONLY — never passed from host) ----
__device__ int   g_deg_i[N_NODES];
__device__ int   g_rp[N_NODES + 1];       // CSR row pointers (by dst)
__device__ int   g_bsum[128];
__device__ int   g_cnt[N_NODES];
__device__ int   g_col[N_EDGES];          // CSR column (src) indices
__device__ float g_inv[N_NODES];
__device__ __align__(16) __half g_xlh[N_NODES * D];  // in @ Wl^T, fp16 (gathered operand)
__device__ __align__(16) float  g_p [N_NODES * D];   // in @ Wr^T + b (fp32)
__device__ __align__(16) float  g_h [N_NODES * D];   // layer-1 output (fp32)

// ---------------- CSR build ----------------

__global__ void k_zero_deg() {
    int i = blockIdx.x * blockDim.x + threadIdx.x;
    if (i < N_NODES) g_deg_i[i] = 0;
}

__global__ void k_deg(const int* __restrict__ dst) {
    int e = blockIdx.x * blockDim.x + threadIdx.x;
    if (e < N_EDGES) atomicAdd(&g_deg_i[dst[e]], 1);
}

// Block-level inclusive scan (1024 wide); writes rp[i+1] (partial) + block totals.
__global__ __launch_bounds__(1024) void k_scan1() {
    __shared__ int s[1024];
    const int t = threadIdx.x, b = blockIdx.x;
    const int i = b * 1024 + t;
    s[t] = (i < N_NODES) ? g_deg_i[i] : 0;
    __syncthreads();
    for (int off = 1; off < 1024; off <<= 1) {
        int u = (t >= off) ? s[t - off] : 0;
        __syncthreads();
        s[t] += u;
        __syncthreads();
    }
    if (i < N_NODES) g_rp[i + 1] = s[t];
    if (t == 1023) g_bsum[b] = s[t];
}

// Scan the block totals (single block, 128 threads >= 98 blocks).
__global__ void k_scan2() {
    __shared__ int s[128];
    const int t = threadIdx.x;
    s[t] = (t < SCAN_NB) ? g_bsum[t] : 0;
    __syncthreads();
    for (int off = 1; off < 128; off <<= 1) {
        int u = (t >= off) ? s[t - off] : 0;
        __syncthreads();
        s[t] += u;
        __syncthreads();
    }
    g_bsum[t] = s[t];
}

// Add block offsets, zero fill counters, compute inv_deg, set rp[0].
__global__ void k_scan3() {
    int i = blockIdx.x * blockDim.x + threadIdx.x;
    if (i < N_NODES) {
        int b = i >> 10;
        if (b > 0) g_rp[i + 1] += g_bsum[b - 1];
        g_cnt[i] = 0;
        g_inv[i] = 1.0f / (float)max(g_deg_i[i], 1);
    }
    if (i == 0) g_rp[0] = 0;
}

__global__ void k_fill(const int* __restrict__ src, const int* __restrict__ dst) {
    int e = blockIdx.x * blockDim.x + threadIdx.x;
    if (e < N_EDGES) {
        const int d = dst[e];
        const int pos = atomicAdd(&g_cnt[d], 1);
        g_col[g_rp[d] + pos] = src[e];
    }
}

// ---------------- dual GEMM, float4-vectorized smem ----------------
// xl = in @ Wl^T (stored fp16),  p = in @ Wr^T + b (fp32).
// LAYER==1: in = x arg; LAYER==2: in = g_h.
template <int LAYER>
__global__ __launch_bounds__(256) void k_gemm(const float* __restrict__ xin,
                                              const float4* __restrict__ Wl,
                                              const float4* __restrict__ Wr,
                                              const float4* __restrict__ b) {
    __shared__ float4 swl[64 * 16];
    __shared__ float4 swr[64 * 16];
    __shared__ float4 sx [64 * 16];

    const float4* in = (LAYER == 1) ? reinterpret_cast<const float4*>(xin)
                                    : reinterpret_cast<const float4*>(g_h);

    const int tid = threadIdx.x;
    const int tx  = tid & 15;     // outs 4*tx .. 4*tx+3
    const int ty  = tid >> 4;     // nodes 4*ty .. 4*ty+3 (within chunk)

    #pragma unroll
    for (int i = tid; i < 1024; i += 256) {
        const int out = i >> 4, k4 = i & 15;
        const int f = (out << 4) | (k4 ^ ((out >> 2) & 15));
        swl[f] = Wl[i];
        swr[f] = Wr[i];
    }
    const float4 bias = b[tx];
    const int base = blockIdx.x * 256;

    for (int chunk = 0; chunk < 4; chunk++) {
        const int cbase = base + chunk * 64;
        __syncthreads();
        #pragma unroll
        for (int i = tid; i < 1024; i += 256) {
            const int gn = cbase + (i >> 4);
            float4 v = make_float4(0.f, 0.f, 0.f, 0.f);
            if (gn < N_NODES) v = in[gn * 16 + (i & 15)];
            sx[i] = v;
        }
        __syncthreads();

        float accl[4][4], accr[4][4];
        #pragma unroll
        for (int r = 0; r < 4; r++) {
            accl[r][0] = 0.f;    accl[r][1] = 0.f;    accl[r][2] = 0.f;    accl[r][3] = 0.f;
            accr[r][0] = bias.x; accr[r][1] = bias.y; accr[r][2] = bias.z; accr[r][3] = bias.w;
        }

        #pragma unroll 2
        for (int k4 = 0; k4 < 16; k4++) {
            float4 a0 = sx[(ty * 4 + 0) * 16 + k4];
            float4 a1 = sx[(ty * 4 + 1) * 16 + k4];
            float4 a2 = sx[(ty * 4 + 2) * 16 + k4];
            float4 a3 = sx[(ty * 4 + 3) * 16 + k4];
            #pragma unroll
            for (int c = 0; c < 4; c++) {
                const int out = tx * 4 + c;
                const int f = (out << 4) | (k4 ^ ((out >> 2) & 15));
                const float4 wl = swl[f];
                const float4 wr = swr[f];
                const float4 av[4] = {a0, a1, a2, a3};
                #pragma unroll
                for (int r = 0; r < 4; r++) {
                    float sl = accl[r][c], sr = accr[r][c];
                    sl = fmaf(av[r].x, wl.x, sl); sr = fmaf(av[r].x, wr.x, sr);
                    sl = fmaf(av[r].y, wl.y, sl); sr = fmaf(av[r].y, wr.y, sr);
                    sl = fmaf(av[r].z, wl.z, sl); sr = fmaf(av[r].z, wr.z, sr);
                    sl = fmaf(av[r].w, wl.w, sl); sr = fmaf(av[r].w, wr.w, sr);
                    accl[r][c] = sl; accr[r][c] = sr;
                }
            }
        }

        #pragma unroll
        for (int r = 0; r < 4; r++) {
            const int gn = cbase + ty * 4 + r;
            if (gn < N_NODES) {
                // xl -> fp16: 4 floats -> 2x half2 -> 8B store
                __half2 h0 = __floats2half2_rn(accl[r][0], accl[r][1]);
                __half2 h1 = __floats2half2_rn(accl[r][2], accl[r][3]);
                uint2 pk;
                pk.x = *reinterpret_cast<uint32_t*>(&h0);
                pk.y = *reinterpret_cast<uint32_t*>(&h1);
                *reinterpret_cast<uint2*>(&g_xlh[gn * D + 4 * tx]) = pk;
                reinterpret_cast<float4*>(g_p)[gn * 16 + tx] =
                    make_float4(accr[r][0], accr[r][1], accr[r][2], accr[r][3]);
            }
        }
    }
}

// ---------------- CSR gather-aggregate + fused epilogue (fp16 gather) ----------------
// One warp per node; lane owns half2 column pair (cols 2*lane, 2*lane+1).
// Per neighbor: warp reads one 128B line (32 x half2). Unroll x4 for MLP.
// FINAL==0: relu, write g_h.  FINAL==1: no relu, write out arg (d_out).
template <int FINAL>
__global__ __launch_bounds__(256) void k_aggr(float2* __restrict__ out_arg) {
    const int warp = threadIdx.x >> 5, lane = threadIdx.x & 31;
    const int node = blockIdx.x * 8 + warp;
    if (node >= N_NODES) return;
    const int s0 = g_rp[node], s1 = g_rp[node + 1];

    const __half2* xl = reinterpret_cast<const __half2*>(g_xlh);

    float2 acc = make_float2(0.f, 0.f);
    int j = s0;
    for (; j + 3 < s1; j += 4) {
        const int n0 = g_col[j + 0];
        const int n1 = g_col[j + 1];
        const int n2 = g_col[j + 2];
        const int n3 = g_col[j + 3];
        const float2 v0 = __half22float2(xl[n0 * 32 + lane]);
        const float2 v1 = __half22float2(xl[n1 * 32 + lane]);
        const float2 v2 = __half22float2(xl[n2 * 32 + lane]);
        const float2 v3 = __half22float2(xl[n3 * 32 + lane]);
        acc.x += (v0.x + v1.x) + (v2.x + v3.x);
        acc.y += (v0.y + v1.y) + (v2.y + v3.y);
    }
    for (; j < s1; j++) {
        const float2 v = __half22float2(xl[g_col[j] * 32 + lane]);
        acc.x += v.x; acc.y += v.y;
    }

    const float inv = g_inv[node];
    const float2 pp = reinterpret_cast<const float2*>(g_p)[node * 32 + lane];
    float2 r;
    r.x = fmaf(acc.x, inv, pp.x);
    r.y = fmaf(acc.y, inv, pp.y);
    if (FINAL == 0) {
        r.x = fmaxf(r.x, 0.f);
        r.y = fmaxf(r.y, 0.f);
        reinterpret_cast<float2*>(g_h)[node * 32 + lane] = r;
    } else {
        out_arg[node * 32 + lane] = r;
    }
}

// ---------------- launch ----------------
extern "C" void kernel_launch(void* const* d_in, const int* in_sizes, int n_in,
                              void* d_out, int out_size) {
    const float* x   = (const float*)d_in[0];
    const int*   ei  = (const int*)  d_in[1];
    const float* W1l = (const float*)d_in[2];
    const float* b1  = (const float*)d_in[3];
    const float* W1r = (const float*)d_in[4];
    const float* W2l = (const float*)d_in[5];
    const float* b2  = (const float*)d_in[6];
    const float* W2r = (const float*)d_in[7];
    const int* src = ei;
    const int* dst = ei + N_EDGES;

    const int NGRID = (N_NODES + 255) / 256;
    const int EGRID = (N_EDGES + 255) / 256;
    const int GEMM_GRID = (N_NODES + 255) / 256;       // 391
    const int AGGR_GRID = (N_NODES + 7) / 8;           // 12500

    // CSR build (by dst)
    k_zero_deg<<<NGRID, 256>>>();
    k_deg<<<EGRID, 256>>>(dst);
    k_scan1<<<SCAN_NB, 1024>>>();
    k_scan2<<<1, 128>>>();
    k_scan3<<<NGRID, 256>>>();
    k_fill<<<EGRID, 256>>>(src, dst);

    // Layer 1
    k_gemm<1><<<GEMM_GRID, 256>>>(x, (const float4*)W1l, (const float4*)W1r, (const float4*)b1);
    k_aggr<0><<<AGGR_GRID, 256>>>(nullptr);

    // Layer 2
    k_gemm<2><<<GEMM_GRID, 256>>>(nullptr, (const float4*)W2l, (const float4*)W2r, (const float4*)b2);
    k_aggr<1><<<AGGR_GRID, 256>>>((float2*)d_out);
}

// round 8
// speedup vs baseline: 4.6818x; 1.2120x over previous
#include <cuda_runtime.h>
#include <cuda_fp16.h>
#include <mma.h>
#include <cstdint>

using namespace nvcuda;

#define N_NODES 100000
#define N_EDGES 1600000
#define D 64
#define NPAD 100096           // 1564 * 64, padded node count
#define SCAN_NB 98            // ceil(100000/1024)

// ---------------- static scratch (device-code access ONLY — never passed from host) ----
__device__ int   g_deg_i[N_NODES];
__device__ int   g_rp[N_NODES + 1];       // CSR row pointers (by dst)
__device__ int   g_bsum[128];
__device__ int   g_cnt[N_NODES];
__device__ int   g_col[N_EDGES];          // CSR column (src) indices
__device__ float g_inv[N_NODES];
__device__ __align__(16) __half g_x16[NPAD * D];   // fp16 copy of x (layer-1 GEMM input)
__device__ __align__(16) __half g_h16[NPAD * D];   // layer-1 output, fp16 (layer-2 GEMM input)
__device__ __align__(16) __half g_xlh[NPAD * D];   // in @ Wl^T, fp16 (gathered operand)
__device__ __align__(16) float  g_p [NPAD * D];    // in @ Wr^T + b (fp32)

// ---------------- CSR build ----------------

__global__ void k_zero_deg() {
    int i = blockIdx.x * blockDim.x + threadIdx.x;
    if (i < N_NODES) g_deg_i[i] = 0;
}

__global__ void k_deg(const int* __restrict__ dst) {
    int e = blockIdx.x * blockDim.x + threadIdx.x;
    if (e < N_EDGES) atomicAdd(&g_deg_i[dst[e]], 1);
}

__global__ __launch_bounds__(1024) void k_scan1() {
    __shared__ int s[1024];
    const int t = threadIdx.x, b = blockIdx.x;
    const int i = b * 1024 + t;
    s[t] = (i < N_NODES) ? g_deg_i[i] : 0;
    __syncthreads();
    for (int off = 1; off < 1024; off <<= 1) {
        int u = (t >= off) ? s[t - off] : 0;
        __syncthreads();
        s[t] += u;
        __syncthreads();
    }
    if (i < N_NODES) g_rp[i + 1] = s[t];
    if (t == 1023) g_bsum[b] = s[t];
}

__global__ void k_scan2() {
    __shared__ int s[128];
    const int t = threadIdx.x;
    s[t] = (t < SCAN_NB) ? g_bsum[t] : 0;
    __syncthreads();
    for (int off = 1; off < 128; off <<= 1) {
        int u = (t >= off) ? s[t - off] : 0;
        __syncthreads();
        s[t] += u;
        __syncthreads();
    }
    g_bsum[t] = s[t];
}

__global__ void k_scan3() {
    int i = blockIdx.x * blockDim.x + threadIdx.x;
    if (i < N_NODES) {
        int b = i >> 10;
        if (b > 0) g_rp[i + 1] += g_bsum[b - 1];
        g_cnt[i] = 0;
        g_inv[i] = 1.0f / (float)max(g_deg_i[i], 1);
    }
    if (i == 0) g_rp[0] = 0;
}

__global__ void k_fill(const int* __restrict__ src, const int* __restrict__ dst) {
    int e = blockIdx.x * blockDim.x + threadIdx.x;
    if (e < N_EDGES) {
        const int d = dst[e];
        const int pos = atomicAdd(&g_cnt[d], 1);
        g_col[g_rp[d] + pos] = src[e];
    }
}

// ---------------- x -> fp16 conversion (pad region zeroed) ----------------
__global__ void k_x2h(const float* __restrict__ x) {
    int i = blockIdx.x * blockDim.x + threadIdx.x;     // half2 index
    const int n2 = NPAD * D / 2;
    if (i < n2) {
        __half2 h = __float2half2_rn(0.f);
        if (i < N_NODES * D / 2) {
            const float2 v = reinterpret_cast<const float2*>(x)[i];
            h = __floats2half2_rn(v.x, v.y);
        }
        reinterpret_cast<__half2*>(g_x16)[i] = h;
    }
}

// ---------------- tensor-core dual GEMM ----------------
// xl = in @ Wl^T (fp16 out),  p = in @ Wr^T + b (fp32 out).
// Block: 256 threads = 8 warps as (4 row-tiles of 16) x (2 matrix halves).
// Per block: 64 nodes x 128 outs. K=64 in 4 steps of m16n16k16. fp32 accum.
template <int LAYER>
__global__ __launch_bounds__(256) void k_gemm_tc(const float* __restrict__ Wl,
                                                 const float* __restrict__ Wr,
                                                 const float* __restrict__ bia) {
    __shared__ __half sw[128 * 72];        // weights: rows 0-63 Wl, 64-127 Wr
    __shared__ __half sx[64 * 72];         // input tile
    __shared__ float  stage[8][256];       // per-warp 16x16 epilogue staging

    const __half* in = (LAYER == 1) ? g_x16 : g_h16;
    const int tid = threadIdx.x;

    // Load + convert weights (coalesced fp32 reads, L2-broadcast across blocks).
    #pragma unroll
    for (int i = tid; i < 128 * 64; i += 256) {
        const int o = i >> 6, k = i & 63;
        const float w = (o < 64) ? Wl[o * 64 + k] : Wr[(o - 64) * 64 + k];
        sw[o * 72 + k] = __float2half(w);
    }
    // Load 64-row input tile (fp16, 16B chunks).
    const int rbase = blockIdx.x * 64;
    #pragma unroll
    for (int i = tid; i < 512; i += 256) {
        const int r = i >> 3, c = i & 7;
        const uint4 v = *reinterpret_cast<const uint4*>(&in[(rbase + r) * D + c * 8]);
        *reinterpret_cast<uint4*>(&sx[r * 72 + c * 8]) = v;
    }
    __syncthreads();

    const int warp = tid >> 5;
    const int wrow = warp & 3;        // row tile 0..3
    const int wcol = warp >> 2;       // 0 = Wl half, 1 = Wr half
    const int lane = tid & 31;

    wmma::fragment<wmma::accumulator, 16, 16, 16, float> c[4];
    #pragma unroll
    for (int i = 0; i < 4; i++) wmma::fill_fragment(c[i], 0.f);

    #pragma unroll
    for (int kk = 0; kk < 4; kk++) {
        wmma::fragment<wmma::matrix_a, 16, 16, 16, __half, wmma::row_major> a;
        wmma::load_matrix_sync(a, &sx[wrow * 16 * 72 + kk * 16], 72);
        #pragma unroll
        for (int ct = 0; ct < 4; ct++) {
            wmma::fragment<wmma::matrix_b, 16, 16, 16, __half, wmma::col_major> bf;
            wmma::load_matrix_sync(bf, &sw[(wcol * 64 + ct * 16) * 72 + kk * 16], 72);
            wmma::mma_sync(c[ct], a, bf, c[ct]);
        }
    }

    // Epilogue: stage each 16x16 fragment in smem, then convert/write.
    #pragma unroll
    for (int ct = 0; ct < 4; ct++) {
        wmma::store_matrix_sync(stage[warp], c[ct], 16, wmma::mem_row_major);
        __syncwarp();
        const int r  = lane >> 1;            // 0..15
        const int cc = (lane & 1) * 8;       // 0 or 8
        const float* sp = &stage[warp][r * 16 + cc];
        const int gn  = rbase + wrow * 16 + r;      // < NPAD always
        const int col = ct * 16 + cc;               // 0..56 within 64
        if (wcol == 0) {
            __half2 h0 = __floats2half2_rn(sp[0], sp[1]);
            __half2 h1 = __floats2half2_rn(sp[2], sp[3]);
            __half2 h2 = __floats2half2_rn(sp[4], sp[5]);
            __half2 h3 = __floats2half2_rn(sp[6], sp[7]);
            uint4 pk;
            pk.x = *reinterpret_cast<uint32_t*>(&h0);
            pk.y = *reinterpret_cast<uint32_t*>(&h1);
            pk.z = *reinterpret_cast<uint32_t*>(&h2);
            pk.w = *reinterpret_cast<uint32_t*>(&h3);
            *reinterpret_cast<uint4*>(&g_xlh[gn * D + col]) = pk;
        } else {
            float4 o0 = make_float4(sp[0] + bia[col + 0], sp[1] + bia[col + 1],
                                    sp[2] + bia[col + 2], sp[3] + bia[col + 3]);
            float4 o1 = make_float4(sp[4] + bia[col + 4], sp[5] + bia[col + 5],
                                    sp[6] + bia[col + 6], sp[7] + bia[col + 7]);
            *reinterpret_cast<float4*>(&g_p[gn * D + col + 0]) = o0;
            *reinterpret_cast<float4*>(&g_p[gn * D + col + 4]) = o1;
        }
        __syncwarp();   // stage reuse
    }
}

// ---------------- CSR gather-aggregate + fused epilogue (fp16 gather) ----------------
// One warp per node; lane owns cols (2*lane, 2*lane+1) as half2.
// FINAL==0: relu, write g_h16 (fp16).  FINAL==1: no relu, write d_out (fp32).
template <int FINAL>
__global__ __launch_bounds__(256) void k_aggr(float2* __restrict__ out_arg) {
    const int warp = threadIdx.x >> 5, lane = threadIdx.x & 31;
    const int node = blockIdx.x * 8 + warp;
    if (node >= N_NODES) return;
    const int s0 = g_rp[node], s1 = g_rp[node + 1];

    const __half2* xl = reinterpret_cast<const __half2*>(g_xlh);

    float2 acc = make_float2(0.f, 0.f);
    int j = s0;
    for (; j + 3 < s1; j += 4) {
        const int n0 = g_col[j + 0];
        const int n1 = g_col[j + 1];
        const int n2 = g_col[j + 2];
        const int n3 = g_col[j + 3];
        const float2 v0 = __half22float2(xl[n0 * 32 + lane]);
        const float2 v1 = __half22float2(xl[n1 * 32 + lane]);
        const float2 v2 = __half22float2(xl[n2 * 32 + lane]);
        const float2 v3 = __half22float2(xl[n3 * 32 + lane]);
        acc.x += (v0.x + v1.x) + (v2.x + v3.x);
        acc.y += (v0.y + v1.y) + (v2.y + v3.y);
    }
    for (; j < s1; j++) {
        const float2 v = __half22float2(xl[g_col[j] * 32 + lane]);
        acc.x += v.x; acc.y += v.y;
    }

    const float inv = g_inv[node];
    const float2 pp = reinterpret_cast<const float2*>(g_p)[node * 32 + lane];
    float2 r;
    r.x = fmaf(acc.x, inv, pp.x);
    r.y = fmaf(acc.y, inv, pp.y);
    if (FINAL == 0) {
        r.x = fmaxf(r.x, 0.f);
        r.y = fmaxf(r.y, 0.f);
        reinterpret_cast<__half2*>(g_h16)[node * 32 + lane] = __floats2half2_rn(r.x, r.y);
    } else {
        out_arg[node * 32 + lane] = r;
    }
}

// ---------------- launch ----------------
extern "C" void kernel_launch(void* const* d_in, const int* in_sizes, int n_in,
                              void* d_out, int out_size) {
    const float* x   = (const float*)d_in[0];
    const int*   ei  = (const int*)  d_in[1];
    const float* W1l = (const float*)d_in[2];
    const float* b1  = (const float*)d_in[3];
    const float* W1r = (const float*)d_in[4];
    const float* W2l = (const float*)d_in[5];
    const float* b2  = (const float*)d_in[6];
    const float* W2r = (const float*)d_in[7];
    const int* src = ei;
    const int* dst = ei + N_EDGES;

    const int NGRID = (N_NODES + 255) / 256;
    const int EGRID = (N_EDGES + 255) / 256;
    const int GEMM_GRID = NPAD / 64;                   // 1564
    const int AGGR_GRID = (N_NODES + 7) / 8;           // 12500
    const int X2H_GRID  = (NPAD * D / 2 + 255) / 256;

    // CSR build (by dst)
    k_zero_deg<<<NGRID, 256>>>();
    k_deg<<<EGRID, 256>>>(dst);
    k_scan1<<<SCAN_NB, 1024>>>();
    k_scan2<<<1, 128>>>();
    k_scan3<<<NGRID, 256>>>();
    k_fill<<<EGRID, 256>>>(src, dst);

    // fp16 input copy
    k_x2h<<<X2H_GRID, 256>>>(x);

    // Layer 1
    k_gemm_tc<1><<<GEMM_GRID, 256>>>(W1l, W1r, b1);
    k_aggr<0><<<AGGR_GRID, 256>>>(nullptr);

    // Layer 2
    k_gemm_tc<2><<<GEMM_GRID, 256>>>(W2l, W2r, b2);
    k_aggr<1><<<AGGR_GRID, 256>>>((float2*)d_out);
}

// round 9
// speedup vs baseline: 5.1490x; 1.0998x over previous
#include <cuda_runtime.h>
#include <cuda_fp16.h>
#include <mma.h>
#include <cstdint>

using namespace nvcuda;

#define N_NODES 100000
#define N_EDGES 1600000
#define D 64
#define NPAD 100096           // 782 * 128, padded node count
#define SCAN_NB 98            // ceil(100000/1024)

// ---------------- static scratch (device-code access ONLY — never passed from host) ----
__device__ int   g_deg_i[N_NODES];
__device__ int   g_rp[N_NODES + 1];       // CSR row pointers (by dst)
__device__ int   g_bsum[128];
__device__ int   g_cnt[N_NODES];          // seeded to rp[i]; atomic slot counters
__device__ int   g_col[N_EDGES];          // CSR column (src) indices
__device__ float g_inv[N_NODES];
__device__ __align__(16) __half g_h16[NPAD * D];   // layer-1 output, fp16 (layer-2 GEMM input)
__device__ __align__(16) __half g_xlh[NPAD * D];   // in @ Wl^T, fp16 (gathered operand)
__device__ __align__(16) float  g_p [NPAD * D];    // in @ Wr^T + b (fp32)

// ---------------- CSR build ----------------

__global__ void k_zero_deg() {
    int i = blockIdx.x * blockDim.x + threadIdx.x;
    if (i < N_NODES) g_deg_i[i] = 0;
}

__global__ void k_deg(const int* __restrict__ dst) {
    int e = blockIdx.x * blockDim.x + threadIdx.x;
    if (e < N_EDGES) atomicAdd(&g_deg_i[dst[e]], 1);
}

__global__ __launch_bounds__(1024) void k_scan1() {
    __shared__ int s[1024];
    const int t = threadIdx.x, b = blockIdx.x;
    const int i = b * 1024 + t;
    s[t] = (i < N_NODES) ? g_deg_i[i] : 0;
    __syncthreads();
    for (int off = 1; off < 1024; off <<= 1) {
        int u = (t >= off) ? s[t - off] : 0;
        __syncthreads();
        s[t] += u;
        __syncthreads();
    }
    if (i < N_NODES) g_rp[i + 1] = s[t];
    if (t == 1023) g_bsum[b] = s[t];
}

__global__ void k_scan2() {
    __shared__ int s[128];
    const int t = threadIdx.x;
    s[t] = (t < SCAN_NB) ? g_bsum[t] : 0;
    __syncthreads();
    for (int off = 1; off < 128; off <<= 1) {
        int u = (t >= off) ? s[t - off] : 0;
        __syncthreads();
        s[t] += u;
        __syncthreads();
    }
    g_bsum[t] = s[t];
}

// Finalize rp, seed g_cnt[i] = rp[i], compute inv_deg.
__global__ void k_scan3() {
    int i = blockIdx.x * blockDim.x + threadIdx.x;
    if (i < N_NODES) {
        int b = i >> 10;
        int rp1 = g_rp[i + 1] + ((b > 0) ? g_bsum[b - 1] : 0);
        g_rp[i + 1] = rp1;
        const int deg = g_deg_i[i];
        g_cnt[i] = rp1 - deg;              // == rp[i]
        g_inv[i] = 1.0f / (float)max(deg, 1);
    }
    if (i == 0) g_rp[0] = 0;
}

__global__ void k_fill(const int* __restrict__ src, const int* __restrict__ dst) {
    int e = blockIdx.x * blockDim.x + threadIdx.x;
    if (e < N_EDGES) {
        const int pos = atomicAdd(&g_cnt[dst[e]], 1);
        g_col[pos] = src[e];
    }
}

// ---------------- tensor-core dual GEMM ----------------
// xl = in @ Wl^T (fp16 out),  p = in @ Wr^T + b (fp32 out).
// Block: 256 threads = 8 warps; 128-node tile; each warp owns a 16-row slice
// across all 128 outs (64 Wl + 64 Wr). K=64 in 4 m16n16k16 steps, fp32 accum.
// LAYER==1: input is fp32 x arg (converted inline); LAYER==2: g_h16.
template <int LAYER>
__global__ __launch_bounds__(256) void k_gemm_tc(const float* __restrict__ xin,
                                                 const float* __restrict__ Wl,
                                                 const float* __restrict__ Wr,
                                                 const float* __restrict__ bia) {
    __shared__ __half sw[128 * 72];        // weights: rows 0-63 Wl, 64-127 Wr
    __shared__ __half sx[128 * 72];        // input tile (128 nodes)
    __shared__ float  stage[8][256];       // per-warp 16x16 epilogue staging

    const int tid = threadIdx.x;
    const int rbase = blockIdx.x * 128;

    // Load + convert weights (coalesced fp32 reads, L2-broadcast across blocks).
    #pragma unroll
    for (int i = tid; i < 128 * 64; i += 256) {
        const int o = i >> 6, k = i & 63;
        const float w = (o < 64) ? Wl[o * 64 + k] : Wr[(o - 64) * 64 + k];
        sw[o * 72 + k] = __float2half(w);
    }
    // Load 128-row input tile.
    if (LAYER == 1) {
        #pragma unroll
        for (int i = tid; i < 128 * 32; i += 256) {    // float2 chunks
            const int r = i >> 5, c2 = i & 31;
            const int gn = rbase + r;
            float2 v = make_float2(0.f, 0.f);
            if (gn < N_NODES) v = reinterpret_cast<const float2*>(xin)[gn * 32 + c2];
            *reinterpret_cast<__half2*>(&sx[r * 72 + c2 * 2]) = __floats2half2_rn(v.x, v.y);
        }
    } else {
        #pragma unroll
        for (int i = tid; i < 128 * 8; i += 256) {     // uint4 = 8 halves
            const int r = i >> 3, c = i & 7;
            const uint4 v = *reinterpret_cast<const uint4*>(&g_h16[(rbase + r) * D + c * 8]);
            *reinterpret_cast<uint4*>(&sx[r * 72 + c * 8]) = v;
        }
    }
    __syncthreads();

    const int warp = tid >> 5;         // row slice: rows warp*16 .. +15
    const int lane = tid & 31;

    wmma::fragment<wmma::accumulator, 16, 16, 16, float> c[8];
    #pragma unroll
    for (int i = 0; i < 8; i++) wmma::fill_fragment(c[i], 0.f);

    #pragma unroll
    for (int kk = 0; kk < 4; kk++) {
        wmma::fragment<wmma::matrix_a, 16, 16, 16, __half, wmma::row_major> a;
        wmma::load_matrix_sync(a, &sx[warp * 16 * 72 + kk * 16], 72);
        #pragma unroll
        for (int ct = 0; ct < 8; ct++) {
            wmma::fragment<wmma::matrix_b, 16, 16, 16, __half, wmma::col_major> bf;
            wmma::load_matrix_sync(bf, &sw[(ct * 16) * 72 + kk * 16], 72);
            wmma::mma_sync(c[ct], a, bf, c[ct]);
        }
    }

    // Epilogue: stage each 16x16 fragment, then convert/write.
    #pragma unroll
    for (int ct = 0; ct < 8; ct++) {
        wmma::store_matrix_sync(stage[warp], c[ct], 16, wmma::mem_row_major);
        __syncwarp();
        const int r  = lane >> 1;            // 0..15
        const int cc = (lane & 1) * 8;       // 0 or 8
        const float* sp = &stage[warp][r * 16 + cc];
        const int gn = rbase + warp * 16 + r;       // < NPAD always
        if (ct < 4) {
            const int col = ct * 16 + cc;           // xl columns 0..56
            __half2 h0 = __floats2half2_rn(sp[0], sp[1]);
            __half2 h1 = __floats2half2_rn(sp[2], sp[3]);
            __half2 h2 = __floats2half2_rn(sp[4], sp[5]);
            __half2 h3 = __floats2half2_rn(sp[6], sp[7]);
            uint4 pk;
            pk.x = *reinterpret_cast<uint32_t*>(&h0);
            pk.y = *reinterpret_cast<uint32_t*>(&h1);
            pk.z = *reinterpret_cast<uint32_t*>(&h2);
            pk.w = *reinterpret_cast<uint32_t*>(&h3);
            *reinterpret_cast<uint4*>(&g_xlh[gn * D + col]) = pk;
        } else {
            const int col = (ct - 4) * 16 + cc;     // p columns 0..56
            float4 o0 = make_float4(sp[0] + bia[col + 0], sp[1] + bia[col + 1],
                                    sp[2] + bia[col + 2], sp[3] + bia[col + 3]);
            float4 o1 = make_float4(sp[4] + bia[col + 4], sp[5] + bia[col + 5],
                                    sp[6] + bia[col + 6], sp[7] + bia[col + 7]);
            *reinterpret_cast<float4*>(&g_p[gn * D + col + 0]) = o0;
            *reinterpret_cast<float4*>(&g_p[gn * D + col + 4]) = o1;
        }
        __syncwarp();   // stage reuse
    }
}

// ---------------- CSR gather-aggregate + fused epilogue (fp16 gather) ----------------
// One warp per node; lane owns cols (2*lane, 2*lane+1) as half2. Unroll x8 for MLP.
// FINAL==0: relu, write g_h16 (fp16).  FINAL==1: no relu, write d_out (fp32).
template <int FINAL>
__global__ __launch_bounds__(256) void k_aggr(float2* __restrict__ out_arg) {
    const int warp = threadIdx.x >> 5, lane = threadIdx.x & 31;
    const int node = blockIdx.x * 8 + warp;
    if (node >= N_NODES) return;
    const int s0 = g_rp[node], s1 = g_rp[node + 1];

    const __half2* xl = reinterpret_cast<const __half2*>(g_xlh);

    float2 acc = make_float2(0.f, 0.f);
    int j = s0;
    for (; j + 7 < s1; j += 8) {
        int n[8];
        #pragma unroll
        for (int u = 0; u < 8; u++) n[u] = g_col[j + u];
        float2 v[8];
        #pragma unroll
        for (int u = 0; u < 8; u++) v[u] = __half22float2(xl[n[u] * 32 + lane]);
        acc.x += ((v[0].x + v[1].x) + (v[2].x + v[3].x)) + ((v[4].x + v[5].x) + (v[6].x + v[7].x));
        acc.y += ((v[0].y + v[1].y) + (v[2].y + v[3].y)) + ((v[4].y + v[5].y) + (v[6].y + v[7].y));
    }
    for (; j < s1; j++) {
        const float2 v = __half22float2(xl[g_col[j] * 32 + lane]);
        acc.x += v.x; acc.y += v.y;
    }

    const float inv = g_inv[node];
    const float2 pp = reinterpret_cast<const float2*>(g_p)[node * 32 + lane];
    float2 r;
    r.x = fmaf(acc.x, inv, pp.x);
    r.y = fmaf(acc.y, inv, pp.y);
    if (FINAL == 0) {
        r.x = fmaxf(r.x, 0.f);
        r.y = fmaxf(r.y, 0.f);
        reinterpret_cast<__half2*>(g_h16)[node * 32 + lane] = __floats2half2_rn(r.x, r.y);
    } else {
        out_arg[node * 32 + lane] = r;
    }
}

// ---------------- launch ----------------
extern "C" void kernel_launch(void* const* d_in, const int* in_sizes, int n_in,
                              void* d_out, int out_size) {
    const float* x   = (const float*)d_in[0];
    const int*   ei  = (const int*)  d_in[1];
    const float* W1l = (const float*)d_in[2];
    const float* b1  = (const float*)d_in[3];
    const float* W1r = (const float*)d_in[4];
    const float* W2l = (const float*)d_in[5];
    const float* b2  = (const float*)d_in[6];
    const float* W2r = (const float*)d_in[7];
    const int* src = ei;
    const int* dst = ei + N_EDGES;

    const int NGRID = (N_NODES + 255) / 256;
    const int EGRID = (N_EDGES + 255) / 256;
    const int GEMM_GRID = NPAD / 128;                  // 782
    const int AGGR_GRID = (N_NODES + 7) / 8;           // 12500

    // CSR build (by dst)
    k_zero_deg<<<NGRID, 256>>>();
    k_deg<<<EGRID, 256>>>(dst);
    k_scan1<<<SCAN_NB, 1024>>>();
    k_scan2<<<1, 128>>>();
    k_scan3<<<NGRID, 256>>>();
    k_fill<<<EGRID, 256>>>(src, dst);

    // Layer 1 (x converted to fp16 inline)
    k_gemm_tc<1><<<GEMM_GRID, 256>>>(x, W1l, W1r, b1);
    k_aggr<0><<<AGGR_GRID, 256>>>(nullptr);

    // Layer 2
    k_gemm_tc<2><<<GEMM_GRID, 256>>>(nullptr, W2l, W2r, b2);
    k_aggr<1><<<AGGR_GRID, 256>>>((float2*)d_out);
}

// round 10
// speedup vs baseline: 5.2307x; 1.0159x over previous
#include <cuda_runtime.h>
#include <cuda_fp16.h>
#include <mma.h>
#include <cstdint>

using namespace nvcuda;

#define N_NODES 100000
#define N_EDGES 1600000
#define D 64
#define NPAD 100096           // 782 * 128, padded node count
#define SCAN_NB 98            // ceil(100000/1024)

// ---------------- static scratch (device-code access ONLY — never passed from host) ----
__device__ int   g_deg_i[N_NODES];
__device__ int   g_rp[N_NODES + 1];       // CSR row pointers (by dst)
__device__ int   g_bsum[128];
__device__ int   g_cnt[N_NODES];          // seeded to rp[i]; atomic slot counters
__device__ int   g_col[N_EDGES];          // CSR column (src) indices
__device__ float g_inv[N_NODES];
__device__ __align__(16) __half g_h16[NPAD * D];   // layer-1 output, fp16 (layer-2 GEMM input)
__device__ __align__(16) __half g_xlh[NPAD * D];   // in @ Wl^T, fp16 (gathered operand)
__device__ __align__(16) float  g_p [NPAD * D];    // in @ Wr^T + b (fp32)

// ---------------- CSR build ----------------

__global__ void k_zero_deg() {
    int i = blockIdx.x * blockDim.x + threadIdx.x;
    if (i < N_NODES) g_deg_i[i] = 0;
}

__global__ void k_deg(const int* __restrict__ dst) {
    int e = blockIdx.x * blockDim.x + threadIdx.x;
    if (e < N_EDGES) atomicAdd(&g_deg_i[dst[e]], 1);
}

__global__ __launch_bounds__(1024) void k_scan1() {
    __shared__ int s[1024];
    const int t = threadIdx.x, b = blockIdx.x;
    const int i = b * 1024 + t;
    s[t] = (i < N_NODES) ? g_deg_i[i] : 0;
    __syncthreads();
    for (int off = 1; off < 1024; off <<= 1) {
        int u = (t >= off) ? s[t - off] : 0;
        __syncthreads();
        s[t] += u;
        __syncthreads();
    }
    if (i < N_NODES) g_rp[i + 1] = s[t];
    if (t == 1023) g_bsum[b] = s[t];
}

// Finalize rp (adding inline prefix of block sums), seed g_cnt[i] = rp[i], inv_deg.
__global__ void k_scan3() {
    int i = blockIdx.x * blockDim.x + threadIdx.x;
    if (i < N_NODES) {
        const int b = i >> 10;
        int off = 0;
        for (int j = 0; j < b; j++) off += g_bsum[j];   // <=97 cached loads
        const int rp1 = g_rp[i + 1] + off;
        g_rp[i + 1] = rp1;
        const int deg = g_deg_i[i];
        g_cnt[i] = rp1 - deg;              // == rp[i]
        g_inv[i] = 1.0f / (float)max(deg, 1);
    }
    if (i == 0) g_rp[0] = 0;
}

__global__ void k_fill(const int* __restrict__ src, const int* __restrict__ dst) {
    int e = blockIdx.x * blockDim.x + threadIdx.x;
    if (e < N_EDGES) {
        const int pos = atomicAdd(&g_cnt[dst[e]], 1);
        g_col[pos] = src[e];
    }
}

// ---------------- tensor-core dual GEMM ----------------
// xl = in @ Wl^T (fp16 out),  p = in @ Wr^T + b (fp32 out).
// Block: 256 threads = 8 warps; 128-node tile; each warp owns a 16-row slice
// across all 128 outs (64 Wl + 64 Wr). K=64 in 4 m16n16k16 steps, fp32 accum.
// LAYER==1: input is fp32 x arg (converted inline); LAYER==2: g_h16.
template <int LAYER>
__global__ __launch_bounds__(256) void k_gemm_tc(const float* __restrict__ xin,
                                                 const float* __restrict__ Wl,
                                                 const float* __restrict__ Wr,
                                                 const float* __restrict__ bia) {
    __shared__ __half sw[128 * 72];        // weights: rows 0-63 Wl, 64-127 Wr
    __shared__ __half sx[128 * 72];        // input tile (128 nodes)
    __shared__ float  stage[8][256];       // per-warp 16x16 epilogue staging

    const int tid = threadIdx.x;
    const int rbase = blockIdx.x * 128;

    // Load + convert weights (coalesced fp32 reads, L2-broadcast across blocks).
    #pragma unroll
    for (int i = tid; i < 128 * 64; i += 256) {
        const int o = i >> 6, k = i & 63;
        const float w = (o < 64) ? Wl[o * 64 + k] : Wr[(o - 64) * 64 + k];
        sw[o * 72 + k] = __float2half(w);
    }
    // Load 128-row input tile.
    if (LAYER == 1) {
        #pragma unroll
        for (int i = tid; i < 128 * 32; i += 256) {    // float2 chunks
            const int r = i >> 5, c2 = i & 31;
            const int gn = rbase + r;
            float2 v = make_float2(0.f, 0.f);
            if (gn < N_NODES) v = reinterpret_cast<const float2*>(xin)[gn * 32 + c2];
            *reinterpret_cast<__half2*>(&sx[r * 72 + c2 * 2]) = __floats2half2_rn(v.x, v.y);
        }
    } else {
        #pragma unroll
        for (int i = tid; i < 128 * 8; i += 256) {     // uint4 = 8 halves
            const int r = i >> 3, c = i & 7;
            const uint4 v = *reinterpret_cast<const uint4*>(&g_h16[(rbase + r) * D + c * 8]);
            *reinterpret_cast<uint4*>(&sx[r * 72 + c * 8]) = v;
        }
    }
    __syncthreads();

    const int warp = tid >> 5;         // row slice: rows warp*16 .. +15
    const int lane = tid & 31;

    wmma::fragment<wmma::accumulator, 16, 16, 16, float> c[8];
    #pragma unroll
    for (int i = 0; i < 8; i++) wmma::fill_fragment(c[i], 0.f);

    #pragma unroll
    for (int kk = 0; kk < 4; kk++) {
        wmma::fragment<wmma::matrix_a, 16, 16, 16, __half, wmma::row_major> a;
        wmma::load_matrix_sync(a, &sx[warp * 16 * 72 + kk * 16], 72);
        #pragma unroll
        for (int ct = 0; ct < 8; ct++) {
            wmma::fragment<wmma::matrix_b, 16, 16, 16, __half, wmma::col_major> bf;
            wmma::load_matrix_sync(bf, &sw[(ct * 16) * 72 + kk * 16], 72);
            wmma::mma_sync(c[ct], a, bf, c[ct]);
        }
    }

    // Epilogue: stage each 16x16 fragment, then convert/write.
    #pragma unroll
    for (int ct = 0; ct < 8; ct++) {
        wmma::store_matrix_sync(stage[warp], c[ct], 16, wmma::mem_row_major);
        __syncwarp();
        const int r  = lane >> 1;            // 0..15
        const int cc = (lane & 1) * 8;       // 0 or 8
        const float* sp = &stage[warp][r * 16 + cc];
        const int gn = rbase + warp * 16 + r;       // < NPAD always
        if (ct < 4) {
            const int col = ct * 16 + cc;           // xl columns 0..56
            __half2 h0 = __floats2half2_rn(sp[0], sp[1]);
            __half2 h1 = __floats2half2_rn(sp[2], sp[3]);
            __half2 h2 = __floats2half2_rn(sp[4], sp[5]);
            __half2 h3 = __floats2half2_rn(sp[6], sp[7]);
            uint4 pk;
            pk.x = *reinterpret_cast<uint32_t*>(&h0);
            pk.y = *reinterpret_cast<uint32_t*>(&h1);
            pk.z = *reinterpret_cast<uint32_t*>(&h2);
            pk.w = *reinterpret_cast<uint32_t*>(&h3);
            *reinterpret_cast<uint4*>(&g_xlh[gn * D + col]) = pk;
        } else {
            const int col = (ct - 4) * 16 + cc;     // p columns 0..56
            float4 o0 = make_float4(sp[0] + bia[col + 0], sp[1] + bia[col + 1],
                                    sp[2] + bia[col + 2], sp[3] + bia[col + 3]);
            float4 o1 = make_float4(sp[4] + bia[col + 4], sp[5] + bia[col + 5],
                                    sp[6] + bia[col + 6], sp[7] + bia[col + 7]);
            *reinterpret_cast<float4*>(&g_p[gn * D + col + 0]) = o0;
            *reinterpret_cast<float4*>(&g_p[gn * D + col + 4]) = o1;
        }
        __syncwarp();   // stage reuse
    }
}

// ---------------- CSR gather-aggregate + fused epilogue (fp16 gather) ----------------
// One warp per node; lane owns cols (2*lane, 2*lane+1) as half2. Unroll x8 for MLP.
// FINAL==0: relu, write g_h16 (fp16).  FINAL==1: no relu, write d_out (fp32).
template <int FINAL>
__global__ __launch_bounds__(256) void k_aggr(float2* __restrict__ out_arg) {
    const int warp = threadIdx.x >> 5, lane = threadIdx.x & 31;
    const int node = blockIdx.x * 8 + warp;
    if (node >= N_NODES) return;
    const int s0 = g_rp[node], s1 = g_rp[node + 1];

    const __half2* xl = reinterpret_cast<const __half2*>(g_xlh);

    float2 acc = make_float2(0.f, 0.f);
    int j = s0;
    for (; j + 7 < s1; j += 8) {
        int n[8];
        #pragma unroll
        for (int u = 0; u < 8; u++) n[u] = g_col[j + u];
        float2 v[8];
        #pragma unroll
        for (int u = 0; u < 8; u++) v[u] = __half22float2(xl[n[u] * 32 + lane]);
        acc.x += ((v[0].x + v[1].x) + (v[2].x + v[3].x)) + ((v[4].x + v[5].x) + (v[6].x + v[7].x));
        acc.y += ((v[0].y + v[1].y) + (v[2].y + v[3].y)) + ((v[4].y + v[5].y) + (v[6].y + v[7].y));
    }
    for (; j < s1; j++) {
        const float2 v = __half22float2(xl[g_col[j] * 32 + lane]);
        acc.x += v.x; acc.y += v.y;
    }

    const float inv = g_inv[node];
    const float2 pp = reinterpret_cast<const float2*>(g_p)[node * 32 + lane];
    float2 r;
    r.x = fmaf(acc.x, inv, pp.x);
    r.y = fmaf(acc.y, inv, pp.y);
    if (FINAL == 0) {
        r.x = fmaxf(r.x, 0.f);
        r.y = fmaxf(r.y, 0.f);
        reinterpret_cast<__half2*>(g_h16)[node * 32 + lane] = __floats2half2_rn(r.x, r.y);
    } else {
        out_arg[node * 32 + lane] = r;
    }
}

// ---------------- launch ----------------
extern "C" void kernel_launch(void* const* d_in, const int* in_sizes, int n_in,
                              void* d_out, int out_size) {
    const float* x   = (const float*)d_in[0];
    const int*   ei  = (const int*)  d_in[1];
    const float* W1l = (const float*)d_in[2];
    const float* b1  = (const float*)d_in[3];
    const float* W1r = (const float*)d_in[4];
    const float* W2l = (const float*)d_in[5];
    const float* b2  = (const float*)d_in[6];
    const float* W2r = (const float*)d_in[7];
    const int* src = ei;
    const int* dst = ei + N_EDGES;

    const int NGRID = (N_NODES + 255) / 256;
    const int EGRID = (N_EDGES + 255) / 256;
    const int GEMM_GRID = NPAD / 128;                  // 782
    const int AGGR_GRID = (N_NODES + 7) / 8;           // 12500

    // One-time host-side resources (no device memory involved).
    static cudaStream_t s_side = nullptr;
    static cudaEvent_t  ev_fork = nullptr, ev_csr = nullptr;
    if (s_side == nullptr) {
        cudaStreamCreateWithFlags(&s_side, cudaStreamNonBlocking);
        cudaEventCreateWithFlags(&ev_fork, cudaEventDisableTiming);
        cudaEventCreateWithFlags(&ev_csr,  cudaEventDisableTiming);
    }

    // Fork: CSR build on side stream, concurrent with layer-1 GEMM on main stream.
    cudaEventRecord(ev_fork, 0);
    cudaStreamWaitEvent(s_side, ev_fork, 0);

    k_zero_deg<<<NGRID, 256, 0, s_side>>>();
    k_deg<<<EGRID, 256, 0, s_side>>>(dst);
    k_scan1<<<SCAN_NB, 1024, 0, s_side>>>();
    k_scan3<<<NGRID, 256, 0, s_side>>>();
    k_fill<<<EGRID, 256, 0, s_side>>>(src, dst);
    cudaEventRecord(ev_csr, s_side);

    // Main stream: layer-1 GEMM (independent of CSR).
    k_gemm_tc<1><<<GEMM_GRID, 256>>>(x, W1l, W1r, b1);

    // Join: aggregation needs both CSR and GEMM-1 results.
    cudaStreamWaitEvent(0, ev_csr, 0);
    k_aggr<0><<<AGGR_GRID, 256>>>(nullptr);

    // Layer 2 (serial chain).
    k_gemm_tc<2><<<GEMM_GRID, 256>>>(nullptr, W2l, W2r, b2);
    k_aggr<1><<<AGGR_GRID, 256>>>((float2*)d_out);
}

// round 12
// speedup vs baseline: 5.3183x; 1.0167x over previous
#include <cuda_runtime.h>
#include <cuda_fp16.h>
#include <mma.h>
#include <cstdint>

using namespace nvcuda;

#define N_NODES 100000
#define N_EDGES 1600000
#define D 64
#define NPAD 100096           // 782 * 128, padded node count
#define SCAN_NB 98            // ceil(100000/1024)

// ---------------- static scratch (device-code access ONLY — never passed from host) ----
// Zero-initialized at load; k_tail restores g_deg_i's zeros each launch.
__device__ int   g_deg_i[N_NODES];
__device__ int   g_bsum[128];             // block totals (overwritten every run)
__device__ int   g_rp[N_NODES + 1];       // CSR row pointers (by dst)
__device__ int   g_cnt[N_NODES];          // seeded to rp[i]; atomic slot counters
__device__ int   g_col[N_EDGES];          // CSR column (src) indices
__device__ float g_inv[N_NODES];
__device__ __align__(16) __half g_h16[NPAD * D];   // layer-1 output, fp16
__device__ __align__(16) __half g_xlh[NPAD * D];   // in @ Wl^T, fp16 (gathered operand)
__device__ __align__(16) float  g_p [NPAD * D];    // in @ Wr^T + b (fp32)

// ---------------- CSR build ----------------

__global__ void k_deg(const int* __restrict__ dst) {
    int e = blockIdx.x * blockDim.x + threadIdx.x;
    if (e < N_EDGES) atomicAdd(&g_deg_i[dst[e]], 1);
}

// Block-level inclusive scan (1024 wide); writes rp[i+1] (partial) + block totals.
__global__ __launch_bounds__(1024) void k_scan1() {
    __shared__ int s[1024];
    const int t = threadIdx.x, b = blockIdx.x;
    const int i = b * 1024 + t;
    s[t] = (i < N_NODES) ? g_deg_i[i] : 0;
    __syncthreads();
    for (int off = 1; off < 1024; off <<= 1) {
        int u = (t >= off) ? s[t - off] : 0;
        __syncthreads();
        s[t] += u;
        __syncthreads();
    }
    if (i < N_NODES) g_rp[i + 1] = s[t];
    if (t == 1023) g_bsum[b] = s[t];
}

// Finalize rp (adding inline prefix of block sums), seed g_cnt[i] = rp[i], inv_deg.
__global__ void k_scan3() {
    int i = blockIdx.x * blockDim.x + threadIdx.x;
    if (i < N_NODES) {
        const int b = i >> 10;
        int off = 0;
        for (int j = 0; j < b; j++) off += g_bsum[j];   // <=97 cached loads
        const int rp1 = g_rp[i + 1] + off;
        g_rp[i + 1] = rp1;
        const int deg = g_deg_i[i];
        g_cnt[i] = rp1 - deg;              // == rp[i]
        g_inv[i] = 1.0f / (float)max(deg, 1);
    }
    if (i == 0) g_rp[0] = 0;
}

__global__ void k_fill(const int* __restrict__ src, const int* __restrict__ dst) {
    int e = blockIdx.x * blockDim.x + threadIdx.x;
    if (e < N_EDGES) {
        const int pos = atomicAdd(&g_cnt[dst[e]], 1);
        g_col[pos] = src[e];
    }
}

// Tail: restore zeroed g_deg_i for the next replay (off the critical path).
__global__ void k_tail() {
    int i = blockIdx.x * blockDim.x + threadIdx.x;
    if (i < N_NODES) g_deg_i[i] = 0;
}

// ---------------- tensor-core dual GEMM ----------------
// xl = in @ Wl^T (fp16 out),  p = in @ Wr^T + b (fp32 out).
// Block: 256 threads = 8 warps; 128-node tile; each warp owns a 16-row slice
// across all 128 outs (64 Wl + 64 Wr). K=64 in 4 m16n16k16 steps, fp32 accum.
// LAYER==1: input is fp32 x arg (converted inline); LAYER==2: g_h16.
template <int LAYER>
__global__ __launch_bounds__(256) void k_gemm_tc(const float* __restrict__ xin,
                                                 const float* __restrict__ Wl,
                                                 const float* __restrict__ Wr,
                                                 const float* __restrict__ bia) {
    __shared__ __half sw[128 * 72];        // weights: rows 0-63 Wl, 64-127 Wr
    __shared__ __half sx[128 * 72];        // input tile (128 nodes)
    __shared__ float  stage[8][256];       // per-warp 16x16 epilogue staging

    const int tid = threadIdx.x;
    const int rbase = blockIdx.x * 128;

    #pragma unroll
    for (int i = tid; i < 128 * 64; i += 256) {
        const int o = i >> 6, k = i & 63;
        const float w = (o < 64) ? Wl[o * 64 + k] : Wr[(o - 64) * 64 + k];
        sw[o * 72 + k] = __float2half(w);
    }
    if (LAYER == 1) {
        #pragma unroll
        for (int i = tid; i < 128 * 32; i += 256) {    // float2 chunks
            const int r = i >> 5, c2 = i & 31;
            const int gn = rbase + r;
            float2 v = make_float2(0.f, 0.f);
            if (gn < N_NODES) v = reinterpret_cast<const float2*>(xin)[gn * 32 + c2];
            *reinterpret_cast<__half2*>(&sx[r * 72 + c2 * 2]) = __floats2half2_rn(v.x, v.y);
        }
    } else {
        #pragma unroll
        for (int i = tid; i < 128 * 8; i += 256) {     // uint4 = 8 halves
            const int r = i >> 3, c = i & 7;
            const uint4 v = *reinterpret_cast<const uint4*>(&g_h16[(rbase + r) * D + c * 8]);
            *reinterpret_cast<uint4*>(&sx[r * 72 + c * 8]) = v;
        }
    }
    __syncthreads();

    const int warp = tid >> 5;
    const int lane = tid & 31;

    wmma::fragment<wmma::accumulator, 16, 16, 16, float> c[8];
    #pragma unroll
    for (int i = 0; i < 8; i++) wmma::fill_fragment(c[i], 0.f);

    #pragma unroll
    for (int kk = 0; kk < 4; kk++) {
        wmma::fragment<wmma::matrix_a, 16, 16, 16, __half, wmma::row_major> a;
        wmma::load_matrix_sync(a, &sx[warp * 16 * 72 + kk * 16], 72);
        #pragma unroll
        for (int ct = 0; ct < 8; ct++) {
            wmma::fragment<wmma::matrix_b, 16, 16, 16, __half, wmma::col_major> bf;
            wmma::load_matrix_sync(bf, &sw[(ct * 16) * 72 + kk * 16], 72);
            wmma::mma_sync(c[ct], a, bf, c[ct]);
        }
    }

    #pragma unroll
    for (int ct = 0; ct < 8; ct++) {
        wmma::store_matrix_sync(stage[warp], c[ct], 16, wmma::mem_row_major);
        __syncwarp();
        const int r  = lane >> 1;
        const int cc = (lane & 1) * 8;
        const float* sp = &stage[warp][r * 16 + cc];
        const int gn = rbase + warp * 16 + r;
        if (ct < 4) {
            const int col = ct * 16 + cc;
            __half2 h0 = __floats2half2_rn(sp[0], sp[1]);
            __half2 h1 = __floats2half2_rn(sp[2], sp[3]);
            __half2 h2 = __floats2half2_rn(sp[4], sp[5]);
            __half2 h3 = __floats2half2_rn(sp[6], sp[7]);
            uint4 pk;
            pk.x = *reinterpret_cast<uint32_t*>(&h0);
            pk.y = *reinterpret_cast<uint32_t*>(&h1);
            pk.z = *reinterpret_cast<uint32_t*>(&h2);
            pk.w = *reinterpret_cast<uint32_t*>(&h3);
            *reinterpret_cast<uint4*>(&g_xlh[gn * D + col]) = pk;
        } else {
            const int col = (ct - 4) * 16 + cc;
            float4 o0 = make_float4(sp[0] + bia[col + 0], sp[1] + bia[col + 1],
                                    sp[2] + bia[col + 2], sp[3] + bia[col + 3]);
            float4 o1 = make_float4(sp[4] + bia[col + 4], sp[5] + bia[col + 5],
                                    sp[6] + bia[col + 6], sp[7] + bia[col + 7]);
            *reinterpret_cast<float4*>(&g_p[gn * D + col + 0]) = o0;
            *reinterpret_cast<float4*>(&g_p[gn * D + col + 4]) = o1;
        }
        __syncwarp();
    }
}

// ---------------- CSR gather-aggregate + fused epilogue (fp16 gather) ----------------
template <int FINAL>
__global__ __launch_bounds__(256) void k_aggr(float2* __restrict__ out_arg) {
    const int warp = threadIdx.x >> 5, lane = threadIdx.x & 31;
    const int node = blockIdx.x * 8 + warp;
    if (node >= N_NODES) return;
    const int s0 = g_rp[node], s1 = g_rp[node + 1];

    const __half2* xl = reinterpret_cast<const __half2*>(g_xlh);

    float2 acc = make_float2(0.f, 0.f);
    int j = s0;
    for (; j + 7 < s1; j += 8) {
        int n[8];
        #pragma unroll
        for (int u = 0; u < 8; u++) n[u] = g_col[j + u];
        float2 v[8];
        #pragma unroll
        for (int u = 0; u < 8; u++) v[u] = __half22float2(xl[n[u] * 32 + lane]);
        acc.x += ((v[0].x + v[1].x) + (v[2].x + v[3].x)) + ((v[4].x + v[5].x) + (v[6].x + v[7].x));
        acc.y += ((v[0].y + v[1].y) + (v[2].y + v[3].y)) + ((v[4].y + v[5].y) + (v[6].y + v[7].y));
    }
    for (; j < s1; j++) {
        const float2 v = __half22float2(xl[g_col[j] * 32 + lane]);
        acc.x += v.x; acc.y += v.y;
    }

    const float inv = g_inv[node];
    const float2 pp = reinterpret_cast<const float2*>(g_p)[node * 32 + lane];
    float2 r;
    r.x = fmaf(acc.x, inv, pp.x);
    r.y = fmaf(acc.y, inv, pp.y);
    if (FINAL == 0) {
        r.x = fmaxf(r.x, 0.f);
        r.y = fmaxf(r.y, 0.f);
        reinterpret_cast<__half2*>(g_h16)[node * 32 + lane] = __floats2half2_rn(r.x, r.y);
    } else {
        out_arg[node * 32 + lane] = r;
    }
}

// ---------------- launch ----------------
extern "C" void kernel_launch(void* const* d_in, const int* in_sizes, int n_in,
                              void* d_out, int out_size) {
    const float* x   = (const float*)d_in[0];
    const int*   ei  = (const int*)  d_in[1];
    const float* W1l = (const float*)d_in[2];
    const float* b1  = (const float*)d_in[3];
    const float* W1r = (const float*)d_in[4];
    const float* W2l = (const float*)d_in[5];
    const float* b2  = (const float*)d_in[6];
    const float* W2r = (const float*)d_in[7];
    const int* src = ei;
    const int* dst = ei + N_EDGES;

    const int NGRID = (N_NODES + 255) / 256;
    const int EGRID = (N_EDGES + 255) / 256;
    const int GEMM_GRID = NPAD / 128;                  // 782
    const int AGGR_GRID = (N_NODES + 7) / 8;           // 12500

    // One-time host-side resources (no device memory involved).
    static cudaStream_t s_side = nullptr;
    static cudaEvent_t  ev_fork = nullptr, ev_csr = nullptr, ev_tail = nullptr;
    if (s_side == nullptr) {
        cudaStreamCreateWithFlags(&s_side, cudaStreamNonBlocking);
        cudaEventCreateWithFlags(&ev_fork, cudaEventDisableTiming);
        cudaEventCreateWithFlags(&ev_csr,  cudaEventDisableTiming);
        cudaEventCreateWithFlags(&ev_tail, cudaEventDisableTiming);
    }

    // Fork: CSR build on side stream, concurrent with layer-1 GEMM on main stream.
    cudaEventRecord(ev_fork, 0);
    cudaStreamWaitEvent(s_side, ev_fork, 0);

    k_deg<<<EGRID, 256, 0, s_side>>>(dst);          // g_deg_i zeroed by prior tail / static init
    k_scan1<<<SCAN_NB, 1024, 0, s_side>>>();
    k_scan3<<<NGRID, 256, 0, s_side>>>();
    k_fill<<<EGRID, 256, 0, s_side>>>(src, dst);
    cudaEventRecord(ev_csr, s_side);
    k_tail<<<NGRID, 256, 0, s_side>>>();            // re-zero g_deg_i; hidden under aggr0
    cudaEventRecord(ev_tail, s_side);

    // Main stream: layer-1 GEMM (independent of CSR).
    k_gemm_tc<1><<<GEMM_GRID, 256>>>(x, W1l, W1r, b1);

    // Join: aggregation needs both CSR and GEMM-1 results.
    cudaStreamWaitEvent(0, ev_csr, 0);
    k_aggr<0><<<AGGR_GRID, 256>>>(nullptr);

    // Layer 2 (serial chain).
    k_gemm_tc<2><<<GEMM_GRID, 256>>>(nullptr, W2l, W2r, b2);
    k_aggr<1><<<AGGR_GRID, 256>>>((float2*)d_out);

    // Final join so capture ends with all side-stream work owned by the main stream.
    cudaStreamWaitEvent(0, ev_tail, 0);
}

// round 14
// speedup vs baseline: 5.4367x; 1.0223x over previous
#include <cuda_runtime.h>
#include <cuda_fp16.h>
#include <mma.h>
#include <cstdint>

using namespace nvcuda;

#define N_NODES 100000
#define N_EDGES 1600000
#define D 64
#define NPAD 100096           // 782 * 128, padded node count
#define SCAN_NB 98            // ceil(100000/1024)

// ---------------- static scratch (device-code access ONLY — never passed from host) ----
// Zero-initialized at load; k_tail restores g_deg_i's zeros each launch.
__device__ int   g_deg_i[N_NODES];
__device__ int   g_bsum[128];             // block totals (overwritten every run)
__device__ int   g_rp[N_NODES + 1];       // CSR row pointers (by dst)
__device__ int   g_epos[N_EDGES];         // per-edge within-dst position
__device__ int   g_col[N_EDGES];          // CSR column (src) indices
__device__ float g_inv[N_NODES];
__device__ __align__(16) __half g_h16[NPAD * D];   // layer-1 output, fp16
__device__ __align__(16) __half g_xlh[NPAD * D];   // in @ Wl^T, fp16 (gathered operand)
__device__ __align__(16) float  g_p [NPAD * D];    // in @ Wr^T + b (fp32)

// ---------------- CSR build ----------------

// Degree count + per-edge slot assignment (atomic return value = position).
__global__ void k_pos(const int* __restrict__ dst) {
    int i = blockIdx.x * blockDim.x + threadIdx.x;
    if (i < N_EDGES / 2) {
        const int2 d = reinterpret_cast<const int2*>(dst)[i];
        const int p0 = atomicAdd(&g_deg_i[d.x], 1);
        const int p1 = atomicAdd(&g_deg_i[d.y], 1);
        reinterpret_cast<int2*>(g_epos)[i] = make_int2(p0, p1);
    }
}

// Block-level inclusive scan (1024 wide); writes rp[i+1] (partial) + block totals.
__global__ __launch_bounds__(1024) void k_scan1() {
    __shared__ int s[1024];
    const int t = threadIdx.x, b = blockIdx.x;
    const int i = b * 1024 + t;
    s[t] = (i < N_NODES) ? g_deg_i[i] : 0;
    __syncthreads();
    for (int off = 1; off < 1024; off <<= 1) {
        int u = (t >= off) ? s[t - off] : 0;
        __syncthreads();
        s[t] += u;
        __syncthreads();
    }
    if (i < N_NODES) g_rp[i + 1] = s[t];
    if (t == 1023) g_bsum[b] = s[t];
}

// Finalize rp (adding inline prefix of block sums, smem-staged) + inv_deg.
__global__ void k_scan3() {
    __shared__ int sb[128];
    const int t = threadIdx.x;
    if (t < 128) sb[t] = g_bsum[t];
    __syncthreads();
    int i = blockIdx.x * blockDim.x + t;
    if (i < N_NODES) {
        const int b = i >> 10;
        int off = 0;
        for (int j = 0; j < b; j++) off += sb[j];   // <=97 smem adds
        g_rp[i + 1] += off;
        g_inv[i] = 1.0f / (float)max(g_deg_i[i], 1);
    }
    if (i == 0) g_rp[0] = 0;
}

// Atomic-free fill: slot = rp[dst] + epos[e].
__global__ void k_fill(const int* __restrict__ src, const int* __restrict__ dst) {
    int i = blockIdx.x * blockDim.x + threadIdx.x;
    if (i < N_EDGES / 2) {
        const int2 s = reinterpret_cast<const int2*>(src)[i];
        const int2 d = reinterpret_cast<const int2*>(dst)[i];
        const int2 p = reinterpret_cast<const int2*>(g_epos)[i];
        g_col[g_rp[d.x] + p.x] = s.x;
        g_col[g_rp[d.y] + p.y] = s.y;
    }
}

// Tail: restore zeroed g_deg_i for the next replay (off the critical path).
__global__ void k_tail() {
    int i = blockIdx.x * blockDim.x + threadIdx.x;
    if (i < N_NODES) g_deg_i[i] = 0;
}

// ---------------- tensor-core dual GEMM ----------------
// xl = in @ Wl^T (fp16 out),  p = in @ Wr^T + b (fp32 out).
// Block: 256 threads = 8 warps; 128-node tile; each warp owns a 16-row slice
// across all 128 outs (64 Wl + 64 Wr). K=64 in 4 m16n16k16 steps, fp32 accum.
// LAYER==1: input is fp32 x arg (converted inline); LAYER==2: g_h16.
template <int LAYER>
__global__ __launch_bounds__(256) void k_gemm_tc(const float* __restrict__ xin,
                                                 const float* __restrict__ Wl,
                                                 const float* __restrict__ Wr,
                                                 const float* __restrict__ bia) {
    __shared__ __half sw[128 * 72];        // weights: rows 0-63 Wl, 64-127 Wr
    __shared__ __half sx[128 * 72];        // input tile (128 nodes)
    __shared__ float  stage[8][256];       // per-warp 16x16 epilogue staging

    const int tid = threadIdx.x;
    const int rbase = blockIdx.x * 128;

    #pragma unroll
    for (int i = tid; i < 128 * 64; i += 256) {
        const int o = i >> 6, k = i & 63;
        const float w = (o < 64) ? Wl[o * 64 + k] : Wr[(o - 64) * 64 + k];
        sw[o * 72 + k] = __float2half(w);
    }
    if (LAYER == 1) {
        #pragma unroll
        for (int i = tid; i < 128 * 32; i += 256) {    // float2 chunks
            const int r = i >> 5, c2 = i & 31;
            const int gn = rbase + r;
            float2 v = make_float2(0.f, 0.f);
            if (gn < N_NODES) v = reinterpret_cast<const float2*>(xin)[gn * 32 + c2];
            *reinterpret_cast<__half2*>(&sx[r * 72 + c2 * 2]) = __floats2half2_rn(v.x, v.y);
        }
    } else {
        #pragma unroll
        for (int i = tid; i < 128 * 8; i += 256) {     // uint4 = 8 halves
            const int r = i >> 3, c = i & 7;
            const uint4 v = *reinterpret_cast<const uint4*>(&g_h16[(rbase + r) * D + c * 8]);
            *reinterpret_cast<uint4*>(&sx[r * 72 + c * 8]) = v;
        }
    }
    __syncthreads();

    const int warp = tid >> 5;
    const int lane = tid & 31;

    wmma::fragment<wmma::accumulator, 16, 16, 16, float> c[8];
    #pragma unroll
    for (int i = 0; i < 8; i++) wmma::fill_fragment(c[i], 0.f);

    #pragma unroll
    for (int kk = 0; kk < 4; kk++) {
        wmma::fragment<wmma::matrix_a, 16, 16, 16, __half, wmma::row_major> a;
        wmma::load_matrix_sync(a, &sx[warp * 16 * 72 + kk * 16], 72);
        #pragma unroll
        for (int ct = 0; ct < 8; ct++) {
            wmma::fragment<wmma::matrix_b, 16, 16, 16, __half, wmma::col_major> bf;
            wmma::load_matrix_sync(bf, &sw[(ct * 16) * 72 + kk * 16], 72);
            wmma::mma_sync(c[ct], a, bf, c[ct]);
        }
    }

    #pragma unroll
    for (int ct = 0; ct < 8; ct++) {
        wmma::store_matrix_sync(stage[warp], c[ct], 16, wmma::mem_row_major);
        __syncwarp();
        const int r  = lane >> 1;
        const int cc = (lane & 1) * 8;
        const float* sp = &stage[warp][r * 16 + cc];
        const int gn = rbase + warp * 16 + r;
        if (ct < 4) {
            const int col = ct * 16 + cc;
            __half2 h0 = __floats2half2_rn(sp[0], sp[1]);
            __half2 h1 = __floats2half2_rn(sp[2], sp[3]);
            __half2 h2 = __floats2half2_rn(sp[4], sp[5]);
            __half2 h3 = __floats2half2_rn(sp[6], sp[7]);
            uint4 pk;
            pk.x = *reinterpret_cast<uint32_t*>(&h0);
            pk.y = *reinterpret_cast<uint32_t*>(&h1);
            pk.z = *reinterpret_cast<uint32_t*>(&h2);
            pk.w = *reinterpret_cast<uint32_t*>(&h3);
            *reinterpret_cast<uint4*>(&g_xlh[gn * D + col]) = pk;
        } else {
            const int col = (ct - 4) * 16 + cc;
            float4 o0 = make_float4(sp[0] + bia[col + 0], sp[1] + bia[col + 1],
                                    sp[2] + bia[col + 2], sp[3] + bia[col + 3]);
            float4 o1 = make_float4(sp[4] + bia[col + 4], sp[5] + bia[col + 5],
                                    sp[6] + bia[col + 6], sp[7] + bia[col + 7]);
            *reinterpret_cast<float4*>(&g_p[gn * D + col + 0]) = o0;
            *reinterpret_cast<float4*>(&g_p[gn * D + col + 4]) = o1;
        }
        __syncwarp();
    }
}

// ---------------- CSR gather-aggregate + fused epilogue (fp16 gather) ----------------
template <int FINAL>
__global__ __launch_bounds__(256) void k_aggr(float2* __restrict__ out_arg) {
    const int warp = threadIdx.x >> 5, lane = threadIdx.x & 31;
    const int node = blockIdx.x * 8 + warp;
    if (node >= N_NODES) return;
    const int s0 = g_rp[node], s1 = g_rp[node + 1];

    const __half2* xl = reinterpret_cast<const __half2*>(g_xlh);

    float2 acc = make_float2(0.f, 0.f);
    int j = s0;
    for (; j + 7 < s1; j += 8) {
        int n[8];
        #pragma unroll
        for (int u = 0; u < 8; u++) n[u] = g_col[j + u];
        float2 v[8];
        #pragma unroll
        for (int u = 0; u < 8; u++) v[u] = __half22float2(xl[n[u] * 32 + lane]);
        acc.x += ((v[0].x + v[1].x) + (v[2].x + v[3].x)) + ((v[4].x + v[5].x) + (v[6].x + v[7].x));
        acc.y += ((v[0].y + v[1].y) + (v[2].y + v[3].y)) + ((v[4].y + v[5].y) + (v[6].y + v[7].y));
    }
    for (; j < s1; j++) {
        const float2 v = __half22float2(xl[g_col[j] * 32 + lane]);
        acc.x += v.x; acc.y += v.y;
    }

    const float inv = g_inv[node];
    const float2 pp = reinterpret_cast<const float2*>(g_p)[node * 32 + lane];
    float2 r;
    r.x = fmaf(acc.x, inv, pp.x);
    r.y = fmaf(acc.y, inv, pp.y);
    if (FINAL == 0) {
        r.x = fmaxf(r.x, 0.f);
        r.y = fmaxf(r.y, 0.f);
        reinterpret_cast<__half2*>(g_h16)[node * 32 + lane] = __floats2half2_rn(r.x, r.y);
    } else {
        out_arg[node * 32 + lane] = r;
    }
}

// ---------------- launch ----------------
extern "C" void kernel_launch(void* const* d_in, const int* in_sizes, int n_in,
                              void* d_out, int out_size) {
    const float* x   = (const float*)d_in[0];
    const int*   ei  = (const int*)  d_in[1];
    const float* W1l = (const float*)d_in[2];
    const float* b1  = (const float*)d_in[3];
    const float* W1r = (const float*)d_in[4];
    const float* W2l = (const float*)d_in[5];
    const float* b2  = (const float*)d_in[6];
    const float* W2r = (const float*)d_in[7];
    const int* src = ei;
    const int* dst = ei + N_EDGES;

    const int NGRID = (N_NODES + 255) / 256;
    const int E2GRID = (N_EDGES / 2 + 255) / 256;      // 3125
    const int GEMM_GRID = NPAD / 128;                  // 782
    const int AGGR_GRID = (N_NODES + 7) / 8;           // 12500

    // One-time host-side resources (no device memory involved).
    static cudaStream_t s_side = nullptr;
    static cudaEvent_t  ev_fork = nullptr, ev_csr = nullptr, ev_tail = nullptr;
    if (s_side == nullptr) {
        cudaStreamCreateWithFlags(&s_side, cudaStreamNonBlocking);
        cudaEventCreateWithFlags(&ev_fork, cudaEventDisableTiming);
        cudaEventCreateWithFlags(&ev_csr,  cudaEventDisableTiming);
        cudaEventCreateWithFlags(&ev_tail, cudaEventDisableTiming);
    }

    // Fork: CSR build on side stream, concurrent with layer-1 GEMM on main stream.
    cudaEventRecord(ev_fork, 0);
    cudaStreamWaitEvent(s_side, ev_fork, 0);

    k_pos<<<E2GRID, 256, 0, s_side>>>(dst);         // g_deg_i zeroed by prior tail / static init
    k_scan1<<<SCAN_NB, 1024, 0, s_side>>>();
    k_scan3<<<NGRID, 256, 0, s_side>>>();
    k_fill<<<E2GRID, 256, 0, s_side>>>(src, dst);
    cudaEventRecord(ev_csr, s_side);
    k_tail<<<NGRID, 256, 0, s_side>>>();            // re-zero g_deg_i; hidden under aggr0
    cudaEventRecord(ev_tail, s_side);

    // Main stream: layer-1 GEMM (independent of CSR).
    k_gemm_tc<1><<<GEMM_GRID, 256>>>(x, W1l, W1r, b1);

    // Join: aggregation needs both CSR and GEMM-1 results.
    cudaStreamWaitEvent(0, ev_csr, 0);
    k_aggr<0><<<AGGR_GRID, 256>>>(nullptr);

    // Layer 2 (serial chain).
    k_gemm_tc<2><<<GEMM_GRID, 256>>>(nullptr, W2l, W2r, b2);
    k_aggr<1><<<AGGR_GRID, 256>>>((float2*)d_out);

    // Final join so capture ends with all side-stream work owned by the main stream.
    cudaStreamWaitEvent(0, ev_tail, 0);
}